// round 11
// baseline (speedup 1.0000x reference)
#include <cuda_runtime.h>
#include <cuda_fp16.h>
#include <math.h>
#include <stdint.h>

// ---------------- Problem constants ----------------
#define BB      2
#define LL      4096
#define DMODEL  1024
#define DSSM    2048
#define DSTATE  128
#define DCONV   4
#define NH      32
#define HD      64
#define CONVDIM (DSSM + 2*DSTATE)          // 2304
#define DPROJ   (2*DSSM + 2*DSTATE + NH)   // 4384
#define EPSV    1e-5f

#define ROWS    (BB*LL)                    // 8192
#define CT      64                         // chunk length
#define NCHUNK  (LL/CT)                    // 64
#define NSLOT   (BB*NH*NCHUNK)             // 4096

// ---------------- Scratch (static device arrays; no allocation) ----------------
__device__ float  g_zxbcdt[(size_t)ROWS * DPROJ];
__device__ float  g_xbc[(size_t)ROWS * CONVDIM];
__device__ float  g_dtT[(size_t)NH * ROWS];
__device__ float  g_ldAT[(size_t)NH * ROWS];
__device__ float  g_y[(size_t)ROWS * DSSM];
__device__ float  g_dH[(size_t)NSLOT * HD * DSTATE];
__device__ float  g_hpre[(size_t)NSLOT * HD * DSTATE];
__device__ float  g_cumlog[(size_t)NSLOT * CT];
__device__ float  g_clend[NSLOT];
__device__ __half g_uh[(size_t)ROWS * DMODEL];
__device__ __half g_Winh[(size_t)DPROJ * DMODEL];
__device__ __half g_gh[(size_t)ROWS * DSSM];
__device__ __half g_Wouth[(size_t)DMODEL * DSSM];

// ---------------- helpers ----------------
__device__ __forceinline__ float silu_f(float x) {
    return x / (1.0f + expf(-x));
}

__device__ __forceinline__ uint32_t smem_u32(const void* p) {
    uint32_t a;
    asm("{ .reg .u64 t; cvta.to.shared.u64 t, %1; cvt.u32.u64 %0, t; }" : "=r"(a) : "l"(p));
    return a;
}

__device__ __forceinline__ void ldsm4(uint32_t &r0, uint32_t &r1, uint32_t &r2, uint32_t &r3,
                                      uint32_t saddr) {
    asm volatile("ldmatrix.sync.aligned.m8n8.x4.shared.b16 {%0,%1,%2,%3}, [%4];"
                 : "=r"(r0), "=r"(r1), "=r"(r2), "=r"(r3)
                 : "r"(saddr));
}

__device__ __forceinline__ void cp_async16(uint32_t dst, const void* src, int srcsize) {
    asm volatile("cp.async.cg.shared.global [%0], [%1], 16, %2;"
                 :: "r"(dst), "l"(src), "r"(srcsize) : "memory");
}

__device__ __forceinline__ void mma16816(float* d, const uint32_t* a, const uint32_t* b) {
    asm volatile(
        "mma.sync.aligned.m16n8k16.row.col.f32.f16.f16.f32 "
        "{%0,%1,%2,%3}, {%4,%5,%6,%7}, {%8,%9}, {%0,%1,%2,%3};"
        : "+f"(d[0]), "+f"(d[1]), "+f"(d[2]), "+f"(d[3])
        : "r"(a[0]), "r"(a[1]), "r"(a[2]), "r"(a[3]), "r"(b[0]), "r"(b[1]));
}

// ---------------- fp16 tensor-core GEMM, 3-stage cp.async pipeline (NT) ----------------
__global__ __launch_bounds__(256) void hgemm_nt_kernel(
    const __half* __restrict__ A, const __half* __restrict__ B, float* __restrict__ C,
    int M, int N, int K)
{
    __shared__ __align__(16) __half As[3][128][40];
    __shared__ __align__(16) __half Bs[3][128][40];

    const int tid  = threadIdx.x;
    const int warp = tid >> 5;
    const int lane = tid & 31;
    const int g    = lane >> 2;
    const int t4   = lane & 3;
    const int wm   = (warp >> 1) * 32;
    const int wn   = (warp & 1) * 64;
    const int m0   = blockIdx.y * 128;
    const int n0   = blockIdx.x * 128;

    const int lm  = lane >> 3;
    const int lr  = lane & 7;
    const int arow = (lm & 1) * 8 + lr;
    const int acol = (lm >> 1) * 8;
    const int brow = (lm >> 1) * 8 + lr;
    const int bcol = (lm & 1) * 8;

    const uint32_t as_b = smem_u32(&As[0][0][0]);
    const uint32_t bs_b = smem_u32(&Bs[0][0][0]);
    const uint32_t BUFB = 128u * 40u * 2u;

    float d[2][8][4];
#pragma unroll
    for (int i = 0; i < 2; i++)
#pragma unroll
        for (int j = 0; j < 8; j++)
#pragma unroll
            for (int v = 0; v < 4; v++) d[i][j][v] = 0.0f;

    const int nch = K >> 5;

    auto stage = [&](int kc, int buf) {
        const int kb = kc << 5;
#pragma unroll
        for (int i = 0; i < 2; i++) {
            const int f   = tid + (i << 8);
            const int row = f >> 2;
            const int seg = f & 3;
            const uint32_t off = (uint32_t)(row * 80 + seg * 16);
            cp_async16(as_b + (uint32_t)buf * BUFB + off,
                       &A[(size_t)(m0 + row) * K + kb + seg * 8], 16);
            const int nr = n0 + row;
            const int ok = (nr < N);
            cp_async16(bs_b + (uint32_t)buf * BUFB + off,
                       &B[(size_t)(ok ? nr : 0) * K + kb + seg * 8], ok ? 16 : 0);
        }
        asm volatile("cp.async.commit_group;" ::: "memory");
    };

    stage(0, 0);
    if (nch > 1) stage(1, 1);

    for (int kc = 0; kc < nch; kc++) {
        const int buf = kc % 3;
        if (kc + 1 < nch) {
            asm volatile("cp.async.wait_group 1;" ::: "memory");
        } else {
            asm volatile("cp.async.wait_group 0;" ::: "memory");
        }
        __syncthreads();
        if (kc + 2 < nch) stage(kc + 2, (kc + 2) % 3);

        const uint32_t ab = as_b + (uint32_t)buf * BUFB;
        const uint32_t bb = bs_b + (uint32_t)buf * BUFB;
#pragma unroll
        for (int s = 0; s < 2; s++) {
            const int kk = s * 16;
            uint32_t af[2][4];
#pragma unroll
            for (int mt = 0; mt < 2; mt++) {
                uint32_t addr = ab + (uint32_t)(((wm + mt * 16 + arow) * 40 + kk + acol) * 2);
                ldsm4(af[mt][0], af[mt][1], af[mt][2], af[mt][3], addr);
            }
            uint32_t bf[8][2];
#pragma unroll
            for (int ntp = 0; ntp < 4; ntp++) {
                uint32_t q0, q1, q2, q3;
                uint32_t addr = bb + (uint32_t)(((wn + ntp * 16 + brow) * 40 + kk + bcol) * 2);
                ldsm4(q0, q1, q2, q3, addr);
                bf[2 * ntp][0]     = q0;  bf[2 * ntp][1]     = q1;
                bf[2 * ntp + 1][0] = q2;  bf[2 * ntp + 1][1] = q3;
            }
#pragma unroll
            for (int mt = 0; mt < 2; mt++) {
#pragma unroll
                for (int nt = 0; nt < 8; nt++) {
                    mma16816(d[mt][nt], af[mt], bf[nt]);
                }
            }
        }
    }

#pragma unroll
    for (int mt = 0; mt < 2; mt++) {
        const int mrow = m0 + wm + mt * 16;
#pragma unroll
        for (int nt = 0; nt < 8; nt++) {
            const int ncol = n0 + wn + nt * 8 + t4 * 2;
            if (ncol < N) {
                *(float2*)&C[(size_t)(mrow + g    ) * N + ncol] =
                    make_float2(d[mt][nt][0], d[mt][nt][1]);
                *(float2*)&C[(size_t)(mrow + g + 8) * N + ncol] =
                    make_float2(d[mt][nt][2], d[mt][nt][3]);
            }
        }
    }
}

// ---------------- fp32 -> fp16 conversion (vectorized) ----------------
__global__ __launch_bounds__(256) void f2h_kernel(const float* __restrict__ src,
                                                  __half* __restrict__ dst, size_t n)
{
    size_t i = ((size_t)blockIdx.x * blockDim.x + threadIdx.x) * 4;
    if (i >= n) return;
    float4 v = *(const float4*)&src[i];
    __half2* d2 = (__half2*)&dst[i];
    d2[0] = __floats2half2_rn(v.x, v.y);
    d2[1] = __floats2half2_rn(v.z, v.w);
}

// ---------------- conv1d (width 4, causal) + bias + SiLU ----------------
__global__ __launch_bounds__(256) void conv_silu_kernel(
    const float* __restrict__ conv_w, const float* __restrict__ conv_b)
{
    size_t idx = (size_t)blockIdx.x * blockDim.x + threadIdx.x;
    if (idx >= (size_t)ROWS * CONVDIM) return;
    int c = (int)(idx % CONVDIM);
    size_t bt = idx / CONVDIM;
    int t = (int)(bt % LL);
    size_t brow0 = (bt - t);

    float accv = conv_b[c];
#pragma unroll
    for (int w = 0; w < DCONV; w++) {
        int ts = t - (DCONV - 1) + w;
        if (ts >= 0) {
            accv = fmaf(g_zxbcdt[(brow0 + ts) * (size_t)DPROJ + DSSM + c],
                        conv_w[c * DCONV + w], accv);
        }
    }
    g_xbc[idx] = silu_f(accv);
}

// ---------------- dt softplus + log-decay (transposed layouts) ----------------
__global__ __launch_bounds__(256) void dt_kernel(
    const float* __restrict__ dt_bias, const float* __restrict__ A_log)
{
    int idx = blockIdx.x * blockDim.x + threadIdx.x;
    if (idx >= ROWS * NH) return;
    int h = idx % NH;
    int r = idx / NH;
    float raw = g_zxbcdt[(size_t)r * DPROJ + DSSM + CONVDIM + h] + dt_bias[h];
    float dt = (raw > 20.0f) ? raw : log1pf(expf(raw));
    float Aneg = -expf(A_log[h]);
    g_dtT[(size_t)h * ROWS + r] = dt;
    g_ldAT[(size_t)h * ROWS + r] = dt * Aneg;
}

// ================= Chunked SSD scan =================

// ---------------- Phase A: per-chunk state increment (fp32, keeps state exact) ----------------
__global__ __launch_bounds__(256) void ssd_phaseA_kernel()
{
    extern __shared__ float sm[];
    float* s_B    = sm;                    // [64][132]
    float* s_wdtx = sm + 64 * 132;         // [64][68]
    float* s_w    = s_wdtx + 64 * 68;      // [64]
    float* s_cl   = s_w + 64;              // [64]

    const int tid = threadIdx.x;
    const int bx  = blockIdx.x;
    const int c   = bx & (NCHUNK - 1);
    const int bh  = bx >> 6;
    const int b   = bh >> 5;
    const int h   = bh & 31;
    const int t0row = b * LL + c * CT;

    if (tid == 0) {
        float cl = 0.f;
        const float* ld = g_ldAT + (size_t)h * ROWS + t0row;
#pragma unroll 4
        for (int t = 0; t < CT; t++) { cl += ld[t]; s_cl[t] = cl; }
    }
#pragma unroll
    for (int i = 0; i < 8; i++) {
        const int f = tid + (i << 8);
        const int row = f >> 5;
        const int q = (f & 31) << 2;
        float4 v = *(const float4*)&g_xbc[(size_t)(t0row + row) * CONVDIM + DSSM + q];
        *(float4*)&s_B[row * 132 + q] = v;
    }
    __syncthreads();

    const float cend = s_cl[CT - 1];
    if (tid < CT) {
        s_w[tid] = expf(cend - s_cl[tid]);
        g_cumlog[(size_t)bx * CT + tid] = s_cl[tid];
        if (tid == 0) g_clend[bx] = cend;
    }
    __syncthreads();

#pragma unroll
    for (int i = 0; i < 16; i++) {
        const int f = tid + (i << 8);
        const int tau = f & 63;
        const int p = f >> 6;
        const float dt = g_dtT[(size_t)h * ROWS + t0row + tau];
        const float xv = g_xbc[(size_t)(t0row + tau) * CONVDIM + h * HD + p];
        s_wdtx[tau * 68 + p] = s_w[tau] * dt * xv;
    }
    __syncthreads();

    const int pp = tid >> 4;
    const int nu = tid & 15;
    const int p0 = pp << 2;
    const int n0 = nu << 3;
    float acc[4][8];
#pragma unroll
    for (int i = 0; i < 4; i++)
#pragma unroll
        for (int j = 0; j < 8; j++) acc[i][j] = 0.f;

#pragma unroll 4
    for (int t4_ = 0; t4_ < 16; t4_++) {
        const int tau = t4_ << 2;
        float4 wv[4];
        float4 bv[4][2];
#pragma unroll
        for (int k = 0; k < 4; k++) {
            wv[k] = *(const float4*)&s_wdtx[(tau + k) * 68 + p0];
            bv[k][0] = *(const float4*)&s_B[(tau + k) * 132 + n0];
            bv[k][1] = *(const float4*)&s_B[(tau + k) * 132 + n0 + 4];
        }
#pragma unroll
        for (int k = 0; k < 4; k++) {
            const float w0 = wv[k].x, w1 = wv[k].y, w2 = wv[k].z, w3 = wv[k].w;
            const float* bp = (const float*)&bv[k][0];
#pragma unroll
            for (int j = 0; j < 8; j++) {
                acc[0][j] = fmaf(w0, bp[j], acc[0][j]);
                acc[1][j] = fmaf(w1, bp[j], acc[1][j]);
                acc[2][j] = fmaf(w2, bp[j], acc[2][j]);
                acc[3][j] = fmaf(w3, bp[j], acc[3][j]);
            }
        }
    }
    float* dh = g_dH + (size_t)bx * (HD * DSTATE);
#pragma unroll
    for (int i = 0; i < 4; i++) {
        *(float4*)&dh[(p0 + i) * DSTATE + n0]     =
            make_float4(acc[i][0], acc[i][1], acc[i][2], acc[i][3]);
        *(float4*)&dh[(p0 + i) * DSTATE + n0 + 4] =
            make_float4(acc[i][4], acc[i][5], acc[i][6], acc[i][7]);
    }
}

// ---------------- Phase B: chunk-level recurrence (parallel over state) ----------------
__global__ __launch_bounds__(256) void ssd_phaseB_kernel()
{
    const int gid = blockIdx.x * 256 + threadIdx.x;
    const int bh  = gid >> 11;
    const int e   = (gid & 2047) << 2;

    float4 h = make_float4(0.f, 0.f, 0.f, 0.f);
    const size_t sbase = (size_t)bh * NCHUNK;
    for (int c = 0; c < NCHUNK; c++) {
        const size_t slot = sbase + c;
        const float4 d4 = *(const float4*)&g_dH[slot * (HD * DSTATE) + e];
        *(float4*)&g_hpre[slot * (HD * DSTATE) + e] = h;
        const float P = expf(g_clend[slot]);
        h.x = fmaf(h.x, P, d4.x);
        h.y = fmaf(h.y, P, d4.y);
        h.z = fmaf(h.z, P, d4.z);
        h.w = fmaf(h.w, P, d4.w);
    }
}

// ---------------- Phase C: per-chunk output on fp16 tensor cores ----------------
// G = C@B^T (NT, natural layouts); Gm = mask/decay(G) -> fp16 smem;
// Y = Gm@dtxT + (et*C)@hpre^T (shared fp32 accumulators); + D*x epilogue.
#define SCW 136   // half stride for 128-col tiles (272B, ldsm conflict-free)
#define SDW 72    // half stride for 64-col tiles (144B, ldsm conflict-free)
#define SMC_BYTES ((4*64*SCW + 2*64*SDW)*2 + 64*4)   // 88320

__global__ __launch_bounds__(256) void ssd_phaseC_kernel(const float* __restrict__ Dp)
{
    extern __shared__ __align__(16) char smc[];
    __half* s_Ch   = (__half*)smc;            // [64][SCW]  C
    __half* s_Cet  = s_Ch   + 64 * SCW;       // [64][SCW]  et*C
    __half* s_Bh   = s_Cet  + 64 * SCW;       // [64][SCW]  B
    __half* s_hh   = s_Bh   + 64 * SCW;       // [64][SCW]  h_prefix [p][n]
    __half* s_dtxT = s_hh   + 64 * SCW;       // [64][SDW]  dtx transposed [p][u]
    __half* s_Gm   = s_dtxT + 64 * SDW;       // [64][SDW]  masked/decayed G
    float*  s_cl   = (float*)(s_Gm + 64 * SDW);  // [64]

    const int tid = threadIdx.x;
    const int warp = tid >> 5;
    const int lane = tid & 31;
    const int g    = lane >> 2;
    const int t4   = lane & 3;
    const int bx  = blockIdx.x;
    const int c   = bx & (NCHUNK - 1);
    const int bh  = bx >> 6;
    const int b   = bh >> 5;
    const int h   = bh & 31;
    const int t0row = b * LL + c * CT;
    const float Dh = Dp[h];

    const int lm  = lane >> 3;
    const int lr  = lane & 7;
    const int arow = (lm & 1) * 8 + lr;
    const int acol = (lm >> 1) * 8;
    const int brow = (lm >> 1) * 8 + lr;
    const int bcol = (lm & 1) * 8;

    if (tid < CT) s_cl[tid] = g_cumlog[(size_t)bx * CT + tid];

    // stage 128-col tiles: C, et*C, B, h_prefix
#pragma unroll
    for (int i = 0; i < 8; i++) {
        const int f = tid + (i << 8);        // 0..2047 float4 slots
        const int row = f >> 5;              // 0..63
        const int q = (f & 31) << 2;         // 0..124
        const float et = expf(g_cumlog[(size_t)bx * CT + row]);
        float4 cv = *(const float4*)&g_xbc[(size_t)(t0row + row) * CONVDIM + DSSM + DSTATE + q];
        *(__half2*)&s_Ch[row * SCW + q]      = __floats2half2_rn(cv.x, cv.y);
        *(__half2*)&s_Ch[row * SCW + q + 2]  = __floats2half2_rn(cv.z, cv.w);
        *(__half2*)&s_Cet[row * SCW + q]     = __floats2half2_rn(et * cv.x, et * cv.y);
        *(__half2*)&s_Cet[row * SCW + q + 2] = __floats2half2_rn(et * cv.z, et * cv.w);
        float4 bv = *(const float4*)&g_xbc[(size_t)(t0row + row) * CONVDIM + DSSM + q];
        *(__half2*)&s_Bh[row * SCW + q]      = __floats2half2_rn(bv.x, bv.y);
        *(__half2*)&s_Bh[row * SCW + q + 2]  = __floats2half2_rn(bv.z, bv.w);
        float4 hv = *(const float4*)&g_hpre[(size_t)bx * (HD * DSTATE) + row * DSTATE + q];
        *(__half2*)&s_hh[row * SCW + q]      = __floats2half2_rn(hv.x, hv.y);
        *(__half2*)&s_hh[row * SCW + q + 2]  = __floats2half2_rn(hv.z, hv.w);
    }
    // stage dtx transposed [p][u]
#pragma unroll
    for (int i = 0; i < 4; i++) {
        const int f = tid + (i << 8);        // 0..1023
        const int u = f >> 4;                // 0..63
        const int p0 = (f & 15) << 2;        // 0..60
        const float dt = g_dtT[(size_t)h * ROWS + t0row + u];
        float4 xv = *(const float4*)&g_xbc[(size_t)(t0row + u) * CONVDIM + h * HD + p0];
        s_dtxT[(p0 + 0) * SDW + u] = __float2half(dt * xv.x);
        s_dtxT[(p0 + 1) * SDW + u] = __float2half(dt * xv.y);
        s_dtxT[(p0 + 2) * SDW + u] = __float2half(dt * xv.z);
        s_dtxT[(p0 + 3) * SDW + u] = __float2half(dt * xv.w);
    }
    __syncthreads();

    const uint32_t b_Ch   = smem_u32(s_Ch);
    const uint32_t b_Cet  = smem_u32(s_Cet);
    const uint32_t b_Bh   = smem_u32(s_Bh);
    const uint32_t b_hh   = smem_u32(s_hh);
    const uint32_t b_dtxT = smem_u32(s_dtxT);
    const uint32_t b_Gm   = smem_u32(s_Gm);

    const int wm = (warp >> 1) * 16;   // t rows (4 warps)
    const int wn = (warp & 1) * 32;    // u / p cols (2 warps)

    // ---- G = C @ B^T ----
    float gacc[4][4];
#pragma unroll
    for (int i = 0; i < 4; i++)
#pragma unroll
        for (int j = 0; j < 4; j++) gacc[i][j] = 0.f;

#pragma unroll
    for (int ks = 0; ks < 8; ks++) {
        const int kk = ks * 16;
        uint32_t af[4];
        ldsm4(af[0], af[1], af[2], af[3],
              b_Ch + (uint32_t)(((wm + arow) * SCW + kk + acol) * 2));
        uint32_t bf[4][2];
#pragma unroll
        for (int ntp = 0; ntp < 2; ntp++) {
            uint32_t q0, q1, q2, q3;
            ldsm4(q0, q1, q2, q3,
                  b_Bh + (uint32_t)(((wn + ntp * 16 + brow) * SCW + kk + bcol) * 2));
            bf[2 * ntp][0] = q0;  bf[2 * ntp][1] = q1;
            bf[2 * ntp + 1][0] = q2;  bf[2 * ntp + 1][1] = q3;
        }
#pragma unroll
        for (int nt = 0; nt < 4; nt++) mma16816(gacc[nt], af, bf[nt]);
    }

    // mask + decay, write Gm (fp16)
    {
        const int ta = wm + g, tb = wm + g + 8;
        const float cta_ = s_cl[ta], ctb_ = s_cl[tb];
#pragma unroll
        for (int nt = 0; nt < 4; nt++) {
            const int u0 = wn + nt * 8 + t4 * 2;
            const float cu0 = s_cl[u0], cu1 = s_cl[u0 + 1];
            float v0 = (u0     <= ta) ? expf(cta_ - cu0) * gacc[nt][0] : 0.f;
            float v1 = (u0 + 1 <= ta) ? expf(cta_ - cu1) * gacc[nt][1] : 0.f;
            float v2 = (u0     <= tb) ? expf(ctb_ - cu0) * gacc[nt][2] : 0.f;
            float v3 = (u0 + 1 <= tb) ? expf(ctb_ - cu1) * gacc[nt][3] : 0.f;
            *(__half2*)&s_Gm[ta * SDW + u0] = __floats2half2_rn(v0, v1);
            *(__half2*)&s_Gm[tb * SDW + u0] = __floats2half2_rn(v2, v3);
        }
    }
    __syncthreads();

    // ---- Y = Gm @ dtxT  +  (et*C) @ hpre^T ----
    float yacc[4][4];
#pragma unroll
    for (int i = 0; i < 4; i++)
#pragma unroll
        for (int j = 0; j < 4; j++) yacc[i][j] = 0.f;

#pragma unroll
    for (int ks = 0; ks < 4; ks++) {          // K = 64 (u)
        const int kk = ks * 16;
        uint32_t af[4];
        ldsm4(af[0], af[1], af[2], af[3],
              b_Gm + (uint32_t)(((wm + arow) * SDW + kk + acol) * 2));
        uint32_t bf[4][2];
#pragma unroll
        for (int ntp = 0; ntp < 2; ntp++) {
            uint32_t q0, q1, q2, q3;
            ldsm4(q0, q1, q2, q3,
                  b_dtxT + (uint32_t)(((wn + ntp * 16 + brow) * SDW + kk + bcol) * 2));
            bf[2 * ntp][0] = q0;  bf[2 * ntp][1] = q1;
            bf[2 * ntp + 1][0] = q2;  bf[2 * ntp + 1][1] = q3;
        }
#pragma unroll
        for (int nt = 0; nt < 4; nt++) mma16816(yacc[nt], af, bf[nt]);
    }
#pragma unroll
    for (int ks = 0; ks < 8; ks++) {          // K = 128 (n)
        const int kk = ks * 16;
        uint32_t af[4];
        ldsm4(af[0], af[1], af[2], af[3],
              b_Cet + (uint32_t)(((wm + arow) * SCW + kk + acol) * 2));
        uint32_t bf[4][2];
#pragma unroll
        for (int ntp = 0; ntp < 2; ntp++) {
            uint32_t q0, q1, q2, q3;
            ldsm4(q0, q1, q2, q3,
                  b_hh + (uint32_t)(((wn + ntp * 16 + brow) * SCW + kk + bcol) * 2));
            bf[2 * ntp][0] = q0;  bf[2 * ntp][1] = q1;
            bf[2 * ntp + 1][0] = q2;  bf[2 * ntp + 1][1] = q3;
        }
#pragma unroll
        for (int nt = 0; nt < 4; nt++) mma16816(yacc[nt], af, bf[nt]);
    }

    // epilogue: + D*x, write g_y
    {
        const int ta = wm + g, tb = wm + g + 8;
#pragma unroll
        for (int nt = 0; nt < 4; nt++) {
            const int p = wn + nt * 8 + t4 * 2;
            float2 xa = *(const float2*)&g_xbc[(size_t)(t0row + ta) * CONVDIM + h * HD + p];
            float2 xb = *(const float2*)&g_xbc[(size_t)(t0row + tb) * CONVDIM + h * HD + p];
            *(float2*)&g_y[(size_t)(t0row + ta) * DSSM + h * HD + p] =
                make_float2(yacc[nt][0] + Dh * xa.x, yacc[nt][1] + Dh * xa.y);
            *(float2*)&g_y[(size_t)(t0row + tb) * DSSM + h * HD + p] =
                make_float2(yacc[nt][2] + Dh * xb.x, yacc[nt][3] + Dh * xb.y);
        }
    }
}

// ---------------- gate (silu(z)) + RMSNorm -> fp16 output for GEMM2 ----------------
__global__ __launch_bounds__(256) void gate_rmsnorm_kernel(const float* __restrict__ norm_w)
{
    const int row = blockIdx.x;
    const int tid = threadIdx.x;
    const int w = tid >> 5, lane = tid & 31;

    float vals[8];
    float ss = 0.f;
#pragma unroll
    for (int i = 0; i < 8; i++) {
        int e = i * 256 + tid;
        float z = g_zxbcdt[(size_t)row * DPROJ + e];
        float yv = g_y[(size_t)row * DSSM + e];
        float g = yv * silu_f(z);
        vals[i] = g;
        ss = fmaf(g, g, ss);
    }
    ss += __shfl_xor_sync(0xffffffffu, ss, 16);
    ss += __shfl_xor_sync(0xffffffffu, ss, 8);
    ss += __shfl_xor_sync(0xffffffffu, ss, 4);
    ss += __shfl_xor_sync(0xffffffffu, ss, 2);
    ss += __shfl_xor_sync(0xffffffffu, ss, 1);

    __shared__ float red[8];
    __shared__ float sscale;
    if (lane == 0) red[w] = ss;
    __syncthreads();
    if (tid == 0) {
        float s = 0.f;
#pragma unroll
        for (int k = 0; k < 8; k++) s += red[k];
        sscale = rsqrtf(s / (float)DSSM + EPSV);
    }
    __syncthreads();
    const float scale = sscale;
#pragma unroll
    for (int i = 0; i < 8; i++) {
        int e = i * 256 + tid;
        g_gh[(size_t)row * DSSM + e] = __float2half(vals[i] * scale * norm_w[e]);
    }
}

// ---------------- entry ----------------
extern "C" void kernel_launch(void* const* d_in, const int* in_sizes, int n_in,
                              void* d_out, int out_size)
{
    const float* u       = (const float*)d_in[0];
    const float* W_in    = (const float*)d_in[1];
    const float* conv_w  = (const float*)d_in[2];
    const float* conv_b  = (const float*)d_in[3];
    const float* dt_bias = (const float*)d_in[4];
    const float* A_log   = (const float*)d_in[5];
    const float* Dp      = (const float*)d_in[6];
    const float* norm_w  = (const float*)d_in[7];
    const float* W_out   = (const float*)d_in[8];
    float* out = (float*)d_out;

    float*  zx;  cudaGetSymbolAddress((void**)&zx,  g_zxbcdt);
    __half* uh;  cudaGetSymbolAddress((void**)&uh,  g_uh);
    __half* wih; cudaGetSymbolAddress((void**)&wih, g_Winh);
    __half* gh;  cudaGetSymbolAddress((void**)&gh,  g_gh);
    __half* woh; cudaGetSymbolAddress((void**)&woh, g_Wouth);

    const int smA = (64 * 132 + 64 * 68 + 64 + 64) * 4;
    cudaFuncSetAttribute(ssd_phaseA_kernel, cudaFuncAttributeMaxDynamicSharedMemorySize, smA);
    cudaFuncSetAttribute(ssd_phaseC_kernel, cudaFuncAttributeMaxDynamicSharedMemorySize, SMC_BYTES);

    // 0) fp16 conversions
    {
        size_t nu = (size_t)ROWS * DMODEL;
        f2h_kernel<<<(unsigned)((nu / 4 + 255) / 256), 256>>>(u, uh, nu);
        size_t nw = (size_t)DPROJ * DMODEL;
        f2h_kernel<<<(unsigned)((nw / 4 + 255) / 256), 256>>>(W_in, wih, nw);
        size_t no = (size_t)DMODEL * DSSM;
        f2h_kernel<<<(unsigned)((no / 4 + 255) / 256), 256>>>(W_out, woh, no);
    }
    // 1) in-projection
    {
        dim3 grid((DPROJ + 127) / 128, ROWS / 128);
        hgemm_nt_kernel<<<grid, 256>>>(uh, wih, zx, ROWS, DPROJ, DMODEL);
    }
    // 2) conv + silu
    {
        size_t total = (size_t)ROWS * CONVDIM;
        conv_silu_kernel<<<(unsigned)((total + 255) / 256), 256>>>(conv_w, conv_b);
    }
    // 3) dt softplus + log decay
    dt_kernel<<<(ROWS * NH + 255) / 256, 256>>>(dt_bias, A_log);
    // 4) chunked SSD scan
    ssd_phaseA_kernel<<<NSLOT, 256, smA>>>();
    ssd_phaseB_kernel<<<512, 256>>>();
    ssd_phaseC_kernel<<<NSLOT, 256, SMC_BYTES>>>(Dp);
    // 5) gate + rmsnorm
    gate_rmsnorm_kernel<<<ROWS, 256>>>(norm_w);
    // 6) out-projection
    {
        dim3 grid(DMODEL / 128, ROWS / 128);
        hgemm_nt_kernel<<<grid, 256>>>(gh, woh, out, ROWS, DMODEL, DSSM);
    }
}

// round 12
// speedup vs baseline: 1.0779x; 1.0779x over previous
#include <cuda_runtime.h>
#include <cuda_fp16.h>
#include <math.h>
#include <stdint.h>

// ---------------- Problem constants ----------------
#define BB      2
#define LL      4096
#define DMODEL  1024
#define DSSM    2048
#define DSTATE  128
#define DCONV   4
#define NH      32
#define HD      64
#define CONVDIM (DSSM + 2*DSTATE)          // 2304
#define DPROJ   (2*DSSM + 2*DSTATE + NH)   // 4384
#define EPSV    1e-5f

#define ROWS    (BB*LL)                    // 8192
#define CT      64                         // chunk length
#define NCHUNK  (LL/CT)                    // 64
#define NSLOT   (BB*NH*NCHUNK)             // 4096

// ---------------- Scratch (static device arrays; no allocation) ----------------
__device__ float  g_zxbcdt[(size_t)ROWS * DPROJ];
__device__ float  g_xbc[(size_t)ROWS * CONVDIM];
__device__ float  g_dtT[(size_t)NH * ROWS];
__device__ float  g_ldAT[(size_t)NH * ROWS];
__device__ float  g_y[(size_t)ROWS * DSSM];
__device__ float  g_dH[(size_t)NSLOT * HD * DSTATE];
__device__ float  g_hpre[(size_t)NSLOT * HD * DSTATE];
__device__ float  g_cumlog[(size_t)NSLOT * CT];
__device__ float  g_clend[NSLOT];
__device__ __half g_uh[(size_t)ROWS * DMODEL];
__device__ __half g_Winh[(size_t)DPROJ * DMODEL];
__device__ __half g_gh[(size_t)ROWS * DSSM];
__device__ __half g_Wouth[(size_t)DMODEL * DSSM];

// ---------------- helpers ----------------
__device__ __forceinline__ float silu_f(float x) {
    return x / (1.0f + expf(-x));
}

__device__ __forceinline__ uint32_t smem_u32(const void* p) {
    uint32_t a;
    asm("{ .reg .u64 t; cvta.to.shared.u64 t, %1; cvt.u32.u64 %0, t; }" : "=r"(a) : "l"(p));
    return a;
}

__device__ __forceinline__ void ldsm4(uint32_t &r0, uint32_t &r1, uint32_t &r2, uint32_t &r3,
                                      uint32_t saddr) {
    asm volatile("ldmatrix.sync.aligned.m8n8.x4.shared.b16 {%0,%1,%2,%3}, [%4];"
                 : "=r"(r0), "=r"(r1), "=r"(r2), "=r"(r3)
                 : "r"(saddr));
}

__device__ __forceinline__ void cp_async16(uint32_t dst, const void* src, int srcsize) {
    asm volatile("cp.async.cg.shared.global [%0], [%1], 16, %2;"
                 :: "r"(dst), "l"(src), "r"(srcsize) : "memory");
}

__device__ __forceinline__ void mma16816(float* d, const uint32_t* a, const uint32_t* b) {
    asm volatile(
        "mma.sync.aligned.m16n8k16.row.col.f32.f16.f16.f32 "
        "{%0,%1,%2,%3}, {%4,%5,%6,%7}, {%8,%9}, {%0,%1,%2,%3};"
        : "+f"(d[0]), "+f"(d[1]), "+f"(d[2]), "+f"(d[3])
        : "r"(a[0]), "r"(a[1]), "r"(a[2]), "r"(a[3]), "r"(b[0]), "r"(b[1]));
}

// ---- packed fp32x2 (FFMA2) helpers ----
__device__ __forceinline__ uint64_t pk2(float x) {
    uint64_t r;
    asm("mov.b64 %0, {%1, %1};" : "=l"(r) : "f"(x));
    return r;
}
__device__ __forceinline__ void fma2(uint64_t &d, uint64_t a, uint64_t b) {
    asm("fma.rn.f32x2 %0, %1, %2, %0;" : "+l"(d) : "l"(a), "l"(b));
}
__device__ __forceinline__ float2 up2(uint64_t v) {
    float2 r;
    asm("mov.b64 {%0, %1}, %2;" : "=f"(r.x), "=f"(r.y) : "l"(v));
    return r;
}

// ---------------- fp16 tensor-core GEMM, 3-stage cp.async pipeline (NT) ----------------
__global__ __launch_bounds__(256) void hgemm_nt_kernel(
    const __half* __restrict__ A, const __half* __restrict__ B, float* __restrict__ C,
    int M, int N, int K)
{
    __shared__ __align__(16) __half As[3][128][40];
    __shared__ __align__(16) __half Bs[3][128][40];

    const int tid  = threadIdx.x;
    const int warp = tid >> 5;
    const int lane = tid & 31;
    const int g    = lane >> 2;
    const int t4   = lane & 3;
    const int wm   = (warp >> 1) * 32;
    const int wn   = (warp & 1) * 64;
    const int m0   = blockIdx.y * 128;
    const int n0   = blockIdx.x * 128;

    const int lm  = lane >> 3;
    const int lr  = lane & 7;
    const int arow = (lm & 1) * 8 + lr;
    const int acol = (lm >> 1) * 8;
    const int brow = (lm >> 1) * 8 + lr;
    const int bcol = (lm & 1) * 8;

    const uint32_t as_b = smem_u32(&As[0][0][0]);
    const uint32_t bs_b = smem_u32(&Bs[0][0][0]);
    const uint32_t BUFB = 128u * 40u * 2u;

    float d[2][8][4];
#pragma unroll
    for (int i = 0; i < 2; i++)
#pragma unroll
        for (int j = 0; j < 8; j++)
#pragma unroll
            for (int v = 0; v < 4; v++) d[i][j][v] = 0.0f;

    const int nch = K >> 5;

    auto stage = [&](int kc, int buf) {
        const int kb = kc << 5;
#pragma unroll
        for (int i = 0; i < 2; i++) {
            const int f   = tid + (i << 8);
            const int row = f >> 2;
            const int seg = f & 3;
            const uint32_t off = (uint32_t)(row * 80 + seg * 16);
            cp_async16(as_b + (uint32_t)buf * BUFB + off,
                       &A[(size_t)(m0 + row) * K + kb + seg * 8], 16);
            const int nr = n0 + row;
            const int ok = (nr < N);
            cp_async16(bs_b + (uint32_t)buf * BUFB + off,
                       &B[(size_t)(ok ? nr : 0) * K + kb + seg * 8], ok ? 16 : 0);
        }
        asm volatile("cp.async.commit_group;" ::: "memory");
    };

    stage(0, 0);
    if (nch > 1) stage(1, 1);

    for (int kc = 0; kc < nch; kc++) {
        const int buf = kc % 3;
        if (kc + 1 < nch) {
            asm volatile("cp.async.wait_group 1;" ::: "memory");
        } else {
            asm volatile("cp.async.wait_group 0;" ::: "memory");
        }
        __syncthreads();
        if (kc + 2 < nch) stage(kc + 2, (kc + 2) % 3);

        const uint32_t ab = as_b + (uint32_t)buf * BUFB;
        const uint32_t bb = bs_b + (uint32_t)buf * BUFB;
#pragma unroll
        for (int s = 0; s < 2; s++) {
            const int kk = s * 16;
            uint32_t af[2][4];
#pragma unroll
            for (int mt = 0; mt < 2; mt++) {
                uint32_t addr = ab + (uint32_t)(((wm + mt * 16 + arow) * 40 + kk + acol) * 2);
                ldsm4(af[mt][0], af[mt][1], af[mt][2], af[mt][3], addr);
            }
            uint32_t bf[8][2];
#pragma unroll
            for (int ntp = 0; ntp < 4; ntp++) {
                uint32_t q0, q1, q2, q3;
                uint32_t addr = bb + (uint32_t)(((wn + ntp * 16 + brow) * 40 + kk + bcol) * 2);
                ldsm4(q0, q1, q2, q3, addr);
                bf[2 * ntp][0]     = q0;  bf[2 * ntp][1]     = q1;
                bf[2 * ntp + 1][0] = q2;  bf[2 * ntp + 1][1] = q3;
            }
#pragma unroll
            for (int mt = 0; mt < 2; mt++) {
#pragma unroll
                for (int nt = 0; nt < 8; nt++) {
                    mma16816(d[mt][nt], af[mt], bf[nt]);
                }
            }
        }
    }

#pragma unroll
    for (int mt = 0; mt < 2; mt++) {
        const int mrow = m0 + wm + mt * 16;
#pragma unroll
        for (int nt = 0; nt < 8; nt++) {
            const int ncol = n0 + wn + nt * 8 + t4 * 2;
            if (ncol < N) {
                *(float2*)&C[(size_t)(mrow + g    ) * N + ncol] =
                    make_float2(d[mt][nt][0], d[mt][nt][1]);
                *(float2*)&C[(size_t)(mrow + g + 8) * N + ncol] =
                    make_float2(d[mt][nt][2], d[mt][nt][3]);
            }
        }
    }
}

// ---------------- fp32 -> fp16 conversion (vectorized) ----------------
__global__ __launch_bounds__(256) void f2h_kernel(const float* __restrict__ src,
                                                  __half* __restrict__ dst, size_t n)
{
    size_t i = ((size_t)blockIdx.x * blockDim.x + threadIdx.x) * 4;
    if (i >= n) return;
    float4 v = *(const float4*)&src[i];
    __half2* d2 = (__half2*)&dst[i];
    d2[0] = __floats2half2_rn(v.x, v.y);
    d2[1] = __floats2half2_rn(v.z, v.w);
}

// ---------------- conv1d (width 4, causal) + bias + SiLU ----------------
__global__ __launch_bounds__(256) void conv_silu_kernel(
    const float* __restrict__ conv_w, const float* __restrict__ conv_b)
{
    size_t idx = (size_t)blockIdx.x * blockDim.x + threadIdx.x;
    if (idx >= (size_t)ROWS * CONVDIM) return;
    int c = (int)(idx % CONVDIM);
    size_t bt = idx / CONVDIM;
    int t = (int)(bt % LL);
    size_t brow0 = (bt - t);

    float accv = conv_b[c];
#pragma unroll
    for (int w = 0; w < DCONV; w++) {
        int ts = t - (DCONV - 1) + w;
        if (ts >= 0) {
            accv = fmaf(g_zxbcdt[(brow0 + ts) * (size_t)DPROJ + DSSM + c],
                        conv_w[c * DCONV + w], accv);
        }
    }
    g_xbc[idx] = silu_f(accv);
}

// ---------------- dt softplus + log-decay (transposed layouts) ----------------
__global__ __launch_bounds__(256) void dt_kernel(
    const float* __restrict__ dt_bias, const float* __restrict__ A_log)
{
    int idx = blockIdx.x * blockDim.x + threadIdx.x;
    if (idx >= ROWS * NH) return;
    int h = idx % NH;
    int r = idx / NH;
    float raw = g_zxbcdt[(size_t)r * DPROJ + DSSM + CONVDIM + h] + dt_bias[h];
    float dt = (raw > 20.0f) ? raw : log1pf(expf(raw));
    float Aneg = -expf(A_log[h]);
    g_dtT[(size_t)h * ROWS + r] = dt;
    g_ldAT[(size_t)h * ROWS + r] = dt * Aneg;
}

// ================= Chunked SSD scan =================

// ---------------- Phase A: per-chunk state increment (fp32, FFMA2 packed) ----------------
__global__ __launch_bounds__(256) void ssd_phaseA_kernel()
{
    extern __shared__ float sm[];
    float* s_B    = sm;                    // [64][132]
    float* s_wdtx = sm + 64 * 132;         // [64][68]
    float* s_w    = s_wdtx + 64 * 68;      // [64]
    float* s_cl   = s_w + 64;              // [64]

    const int tid = threadIdx.x;
    const int bx  = blockIdx.x;
    const int c   = bx & (NCHUNK - 1);
    const int bh  = bx >> 6;
    const int b   = bh >> 5;
    const int h   = bh & 31;
    const int t0row = b * LL + c * CT;

    if (tid == 0) {
        float cl = 0.f;
        const float* ld = g_ldAT + (size_t)h * ROWS + t0row;
#pragma unroll 4
        for (int t = 0; t < CT; t++) { cl += ld[t]; s_cl[t] = cl; }
    }
#pragma unroll
    for (int i = 0; i < 8; i++) {
        const int f = tid + (i << 8);
        const int row = f >> 5;
        const int q = (f & 31) << 2;
        float4 v = *(const float4*)&g_xbc[(size_t)(t0row + row) * CONVDIM + DSSM + q];
        *(float4*)&s_B[row * 132 + q] = v;
    }
    __syncthreads();

    const float cend = s_cl[CT - 1];
    if (tid < CT) {
        s_w[tid] = expf(cend - s_cl[tid]);
        g_cumlog[(size_t)bx * CT + tid] = s_cl[tid];
        if (tid == 0) g_clend[bx] = cend;
    }
    __syncthreads();

#pragma unroll
    for (int i = 0; i < 16; i++) {
        const int f = tid + (i << 8);
        const int tau = f & 63;
        const int p = f >> 6;
        const float dt = g_dtT[(size_t)h * ROWS + t0row + tau];
        const float xv = g_xbc[(size_t)(t0row + tau) * CONVDIM + h * HD + p];
        s_wdtx[tau * 68 + p] = s_w[tau] * dt * xv;
    }
    __syncthreads();

    const int pp = tid >> 4;
    const int nu = tid & 15;
    const int p0 = pp << 2;
    const int n0 = nu << 3;
    uint64_t accp[4][4];     // [i][j-pair]: 4 p-rows x 4 packed pairs (8 n)
#pragma unroll
    for (int i = 0; i < 4; i++)
#pragma unroll
        for (int j = 0; j < 4; j++) accp[i][j] = 0ull;

#pragma unroll 4
    for (int t4_ = 0; t4_ < 16; t4_++) {
        const int tau = t4_ << 2;
        float4 wv[4];
        ulonglong2 bq[4][2];
#pragma unroll
        for (int k = 0; k < 4; k++) {
            wv[k] = *(const float4*)&s_wdtx[(tau + k) * 68 + p0];
            bq[k][0] = *(const ulonglong2*)&s_B[(tau + k) * 132 + n0];
            bq[k][1] = *(const ulonglong2*)&s_B[(tau + k) * 132 + n0 + 4];
        }
#pragma unroll
        for (int k = 0; k < 4; k++) {
            const float* wp = (const float*)&wv[k];
#pragma unroll
            for (int i = 0; i < 4; i++) {
                const uint64_t s = pk2(wp[i]);
                fma2(accp[i][0], s, bq[k][0].x);
                fma2(accp[i][1], s, bq[k][0].y);
                fma2(accp[i][2], s, bq[k][1].x);
                fma2(accp[i][3], s, bq[k][1].y);
            }
        }
    }
    float* dh = g_dH + (size_t)bx * (HD * DSTATE);
#pragma unroll
    for (int i = 0; i < 4; i++) {
        ulonglong2 s0; s0.x = accp[i][0]; s0.y = accp[i][1];
        ulonglong2 s1; s1.x = accp[i][2]; s1.y = accp[i][3];
        *(ulonglong2*)&dh[(p0 + i) * DSTATE + n0]     = s0;
        *(ulonglong2*)&dh[(p0 + i) * DSTATE + n0 + 4] = s1;
    }
}

// ---------------- Phase B: chunk-level recurrence (parallel over state) ----------------
__global__ __launch_bounds__(256) void ssd_phaseB_kernel()
{
    const int gid = blockIdx.x * 256 + threadIdx.x;
    const int bh  = gid >> 11;
    const int e   = (gid & 2047) << 2;

    float4 h = make_float4(0.f, 0.f, 0.f, 0.f);
    const size_t sbase = (size_t)bh * NCHUNK;
    for (int c = 0; c < NCHUNK; c++) {
        const size_t slot = sbase + c;
        const float4 d4 = *(const float4*)&g_dH[slot * (HD * DSTATE) + e];
        *(float4*)&g_hpre[slot * (HD * DSTATE) + e] = h;
        const float P = expf(g_clend[slot]);
        h.x = fmaf(h.x, P, d4.x);
        h.y = fmaf(h.y, P, d4.y);
        h.z = fmaf(h.z, P, d4.z);
        h.w = fmaf(h.w, P, d4.w);
    }
}

// ---------------- Phase C: per-chunk output (fp32, FFMA2 packed) ----------------
__global__ __launch_bounds__(256) void ssd_phaseC_kernel(const float* __restrict__ Dp)
{
    extern __shared__ float sm[];
    float* s_C   = sm;                       // [64][132]
    float* s_BT  = s_C + 64 * 132;           // [128][68]
    float* s_hT  = s_BT + 128 * 68;          // [128][68]
    float* s_dtx = s_hT + 128 * 68;          // [64][68]
    float* s_Gm  = s_dtx + 64 * 68;          // [64][68]
    float* s_cl  = s_Gm + 64 * 68;           // [64]

    const int tid = threadIdx.x;
    const int bx  = blockIdx.x;
    const int c   = bx & (NCHUNK - 1);
    const int bh  = bx >> 6;
    const int b   = bh >> 5;
    const int h   = bh & 31;
    const int t0row = b * LL + c * CT;
    const float Dh = Dp[h];

#pragma unroll
    for (int i = 0; i < 8; i++) {
        const int f = tid + (i << 8);
        const int row = f >> 5;
        const int q = (f & 31) << 2;
        float4 cv = *(const float4*)&g_xbc[(size_t)(t0row + row) * CONVDIM + DSSM + DSTATE + q];
        *(float4*)&s_C[row * 132 + q] = cv;
        float4 bv = *(const float4*)&g_xbc[(size_t)(t0row + row) * CONVDIM + DSSM + q];
        s_BT[(q + 0) * 68 + row] = bv.x;
        s_BT[(q + 1) * 68 + row] = bv.y;
        s_BT[(q + 2) * 68 + row] = bv.z;
        s_BT[(q + 3) * 68 + row] = bv.w;
        const int p = f >> 5;
        float4 hv = *(const float4*)&g_hpre[(size_t)bx * (HD * DSTATE) + p * DSTATE + q];
        s_hT[(q + 0) * 68 + p] = hv.x;
        s_hT[(q + 1) * 68 + p] = hv.y;
        s_hT[(q + 2) * 68 + p] = hv.z;
        s_hT[(q + 3) * 68 + p] = hv.w;
    }
#pragma unroll
    for (int i = 0; i < 16; i++) {
        const int f = tid + (i << 8);
        const int tau = f & 63;
        const int p = f >> 6;
        const float dt = g_dtT[(size_t)h * ROWS + t0row + tau];
        const float xv = g_xbc[(size_t)(t0row + tau) * CONVDIM + h * HD + p];
        s_dtx[tau * 68 + p] = dt * xv;
    }
    if (tid < CT) s_cl[tid] = g_cumlog[(size_t)bx * CT + tid];
    __syncthreads();

    const int tt = tid >> 4;
    const int tu = tid & 15;
    const int t0 = tt << 2;
    const int u0 = tu << 2;

    // ---- G = C @ B^T (packed) ----
    {
        uint64_t gp[4][2];
#pragma unroll
        for (int i = 0; i < 4; i++) { gp[i][0] = 0ull; gp[i][1] = 0ull; }
#pragma unroll 4
        for (int n4 = 0; n4 < 32; n4++) {
            const int n = n4 << 2;
            float4 cv[4];
            ulonglong2 bq[4];
#pragma unroll
            for (int i = 0; i < 4; i++) cv[i] = *(const float4*)&s_C[(t0 + i) * 132 + n];
#pragma unroll
            for (int k = 0; k < 4; k++) bq[k] = *(const ulonglong2*)&s_BT[(n + k) * 68 + u0];
#pragma unroll
            for (int k = 0; k < 4; k++) {
#pragma unroll
                for (int i = 0; i < 4; i++) {
                    const uint64_t s = pk2(((const float*)&cv[i])[k]);
                    fma2(gp[i][0], s, bq[k].x);
                    fma2(gp[i][1], s, bq[k].y);
                }
            }
        }
        // mask + decay, write Gm
#pragma unroll
        for (int i = 0; i < 4; i++) {
            const int t = t0 + i;
            const float clt = s_cl[t];
            const float2 a01 = up2(gp[i][0]);
            const float2 a23 = up2(gp[i][1]);
            const float av[4] = {a01.x, a01.y, a23.x, a23.y};
#pragma unroll
            for (int j = 0; j < 4; j++) {
                const int u = u0 + j;
                s_Gm[t * 68 + u] = (u <= t) ? expf(clt - s_cl[u]) * av[j] : 0.f;
            }
        }
    }
    __syncthreads();

    // ---- Y = Gm @ dtx  +  et * (C @ h^T)  + D*x (packed) ----
    {
        const int p0 = tu << 2;
        uint64_t y1[4][2], y2[4][2];
#pragma unroll
        for (int i = 0; i < 4; i++) {
            y1[i][0] = 0ull; y1[i][1] = 0ull;
            y2[i][0] = 0ull; y2[i][1] = 0ull;
        }

#pragma unroll 4
        for (int u4 = 0; u4 < 16; u4++) {
            const int u = u4 << 2;
            float4 gv[4];
            ulonglong2 dq[4];
#pragma unroll
            for (int i = 0; i < 4; i++) gv[i] = *(const float4*)&s_Gm[(t0 + i) * 68 + u];
#pragma unroll
            for (int k = 0; k < 4; k++) dq[k] = *(const ulonglong2*)&s_dtx[(u + k) * 68 + p0];
#pragma unroll
            for (int k = 0; k < 4; k++) {
#pragma unroll
                for (int i = 0; i < 4; i++) {
                    const uint64_t s = pk2(((const float*)&gv[i])[k]);
                    fma2(y1[i][0], s, dq[k].x);
                    fma2(y1[i][1], s, dq[k].y);
                }
            }
        }
#pragma unroll 4
        for (int n4 = 0; n4 < 32; n4++) {
            const int n = n4 << 2;
            float4 cv[4];
            ulonglong2 hq[4];
#pragma unroll
            for (int i = 0; i < 4; i++) cv[i] = *(const float4*)&s_C[(t0 + i) * 132 + n];
#pragma unroll
            for (int k = 0; k < 4; k++) hq[k] = *(const ulonglong2*)&s_hT[(n + k) * 68 + p0];
#pragma unroll
            for (int k = 0; k < 4; k++) {
#pragma unroll
                for (int i = 0; i < 4; i++) {
                    const uint64_t s = pk2(((const float*)&cv[i])[k]);
                    fma2(y2[i][0], s, hq[k].x);
                    fma2(y2[i][1], s, hq[k].y);
                }
            }
        }
#pragma unroll
        for (int i = 0; i < 4; i++) {
            const int t = t0 + i;
            const int row = t0row + t;
            const float et = expf(s_cl[t]);
            const float2 a01 = up2(y1[i][0]);
            const float2 a23 = up2(y1[i][1]);
            const float2 b01 = up2(y2[i][0]);
            const float2 b23 = up2(y2[i][1]);
            float4 xv = *(const float4*)&g_xbc[(size_t)row * CONVDIM + h * HD + p0];
            float4 y4;
            y4.x = fmaf(et, b01.x, a01.x) + Dh * xv.x;
            y4.y = fmaf(et, b01.y, a01.y) + Dh * xv.y;
            y4.z = fmaf(et, b23.x, a23.x) + Dh * xv.z;
            y4.w = fmaf(et, b23.y, a23.y) + Dh * xv.w;
            *(float4*)&g_y[(size_t)row * DSSM + h * HD + p0] = y4;
        }
    }
}

// ---------------- gate (silu(z)) + RMSNorm -> fp16 output for GEMM2 ----------------
__global__ __launch_bounds__(256) void gate_rmsnorm_kernel(const float* __restrict__ norm_w)
{
    const int row = blockIdx.x;
    const int tid = threadIdx.x;
    const int w = tid >> 5, lane = tid & 31;

    float vals[8];
    float ss = 0.f;
#pragma unroll
    for (int i = 0; i < 8; i++) {
        int e = i * 256 + tid;
        float z = g_zxbcdt[(size_t)row * DPROJ + e];
        float yv = g_y[(size_t)row * DSSM + e];
        float g = yv * silu_f(z);
        vals[i] = g;
        ss = fmaf(g, g, ss);
    }
    ss += __shfl_xor_sync(0xffffffffu, ss, 16);
    ss += __shfl_xor_sync(0xffffffffu, ss, 8);
    ss += __shfl_xor_sync(0xffffffffu, ss, 4);
    ss += __shfl_xor_sync(0xffffffffu, ss, 2);
    ss += __shfl_xor_sync(0xffffffffu, ss, 1);

    __shared__ float red[8];
    __shared__ float sscale;
    if (lane == 0) red[w] = ss;
    __syncthreads();
    if (tid == 0) {
        float s = 0.f;
#pragma unroll
        for (int k = 0; k < 8; k++) s += red[k];
        sscale = rsqrtf(s / (float)DSSM + EPSV);
    }
    __syncthreads();
    const float scale = sscale;
#pragma unroll
    for (int i = 0; i < 8; i++) {
        int e = i * 256 + tid;
        g_gh[(size_t)row * DSSM + e] = __float2half(vals[i] * scale * norm_w[e]);
    }
}

// ---------------- entry ----------------
extern "C" void kernel_launch(void* const* d_in, const int* in_sizes, int n_in,
                              void* d_out, int out_size)
{
    const float* u       = (const float*)d_in[0];
    const float* W_in    = (const float*)d_in[1];
    const float* conv_w  = (const float*)d_in[2];
    const float* conv_b  = (const float*)d_in[3];
    const float* dt_bias = (const float*)d_in[4];
    const float* A_log   = (const float*)d_in[5];
    const float* Dp      = (const float*)d_in[6];
    const float* norm_w  = (const float*)d_in[7];
    const float* W_out   = (const float*)d_in[8];
    float* out = (float*)d_out;

    float*  zx;  cudaGetSymbolAddress((void**)&zx,  g_zxbcdt);
    __half* uh;  cudaGetSymbolAddress((void**)&uh,  g_uh);
    __half* wih; cudaGetSymbolAddress((void**)&wih, g_Winh);
    __half* gh;  cudaGetSymbolAddress((void**)&gh,  g_gh);
    __half* woh; cudaGetSymbolAddress((void**)&woh, g_Wouth);

    const int smA = (64 * 132 + 64 * 68 + 64 + 64) * 4;
    const int smC = (64 * 132 + 128 * 68 + 128 * 68 + 64 * 68 + 64 * 68 + 64) * 4;
    cudaFuncSetAttribute(ssd_phaseA_kernel, cudaFuncAttributeMaxDynamicSharedMemorySize, smA);
    cudaFuncSetAttribute(ssd_phaseC_kernel, cudaFuncAttributeMaxDynamicSharedMemorySize, smC);

    // 0) fp16 conversions
    {
        size_t nu = (size_t)ROWS * DMODEL;
        f2h_kernel<<<(unsigned)((nu / 4 + 255) / 256), 256>>>(u, uh, nu);
        size_t nw = (size_t)DPROJ * DMODEL;
        f2h_kernel<<<(unsigned)((nw / 4 + 255) / 256), 256>>>(W_in, wih, nw);
        size_t no = (size_t)DMODEL * DSSM;
        f2h_kernel<<<(unsigned)((no / 4 + 255) / 256), 256>>>(W_out, woh, no);
    }
    // 1) in-projection
    {
        dim3 grid((DPROJ + 127) / 128, ROWS / 128);
        hgemm_nt_kernel<<<grid, 256>>>(uh, wih, zx, ROWS, DPROJ, DMODEL);
    }
    // 2) conv + silu
    {
        size_t total = (size_t)ROWS * CONVDIM;
        conv_silu_kernel<<<(unsigned)((total + 255) / 256), 256>>>(conv_w, conv_b);
    }
    // 3) dt softplus + log decay
    dt_kernel<<<(ROWS * NH + 255) / 256, 256>>>(dt_bias, A_log);
    // 4) chunked SSD scan
    ssd_phaseA_kernel<<<NSLOT, 256, smA>>>();
    ssd_phaseB_kernel<<<512, 256>>>();
    ssd_phaseC_kernel<<<NSLOT, 256, smC>>>(Dp);
    // 5) gate + rmsnorm
    gate_rmsnorm_kernel<<<ROWS, 256>>>(norm_w);
    // 6) out-projection
    {
        dim3 grid(DMODEL / 128, ROWS / 128);
        hgemm_nt_kernel<<<grid, 256>>>(gh, woh, out, ROWS, DMODEL, DSSM);
    }
}

// round 13
// speedup vs baseline: 1.1084x; 1.0283x over previous
#include <cuda_runtime.h>
#include <cuda_fp16.h>
#include <math.h>
#include <stdint.h>

// ---------------- Problem constants ----------------
#define BB      2
#define LL      4096
#define DMODEL  1024
#define DSSM    2048
#define DSTATE  128
#define DCONV   4
#define NH      32
#define HD      64
#define CONVDIM (DSSM + 2*DSTATE)          // 2304
#define DPROJ   (2*DSSM + 2*DSTATE + NH)   // 4384
#define EPSV    1e-5f

#define ROWS    (BB*LL)                    // 8192
#define CT      64                         // chunk length
#define NCHUNK  (LL/CT)                    // 64
#define NSLOT   (BB*NH*NCHUNK)             // 4096

// ---------------- Scratch (static device arrays; no allocation) ----------------
__device__ float  g_zxbcdt[(size_t)ROWS * DPROJ];
__device__ float  g_xbc[(size_t)ROWS * CONVDIM];
__device__ float  g_dtT[(size_t)NH * ROWS];
__device__ float  g_ldAT[(size_t)NH * ROWS];
__device__ float  g_y[(size_t)ROWS * DSSM];
__device__ float  g_dH[(size_t)NSLOT * HD * DSTATE];
__device__ float  g_hpre[(size_t)NSLOT * HD * DSTATE];
__device__ float  g_cumlog[(size_t)NSLOT * CT];
__device__ float  g_clend[NSLOT];
__device__ __half g_uh[(size_t)ROWS * DMODEL];
__device__ __half g_Winh[(size_t)DPROJ * DMODEL];
__device__ __half g_gh[(size_t)ROWS * DSSM];
__device__ __half g_Wouth[(size_t)DMODEL * DSSM];

// ---------------- helpers ----------------
__device__ __forceinline__ float silu_f(float x) {
    return x / (1.0f + expf(-x));
}

__device__ __forceinline__ uint32_t smem_u32(const void* p) {
    uint32_t a;
    asm("{ .reg .u64 t; cvta.to.shared.u64 t, %1; cvt.u32.u64 %0, t; }" : "=r"(a) : "l"(p));
    return a;
}

__device__ __forceinline__ void ldsm4(uint32_t &r0, uint32_t &r1, uint32_t &r2, uint32_t &r3,
                                      uint32_t saddr) {
    asm volatile("ldmatrix.sync.aligned.m8n8.x4.shared.b16 {%0,%1,%2,%3}, [%4];"
                 : "=r"(r0), "=r"(r1), "=r"(r2), "=r"(r3)
                 : "r"(saddr));
}

__device__ __forceinline__ void cp_async16(uint32_t dst, const void* src, int srcsize) {
    asm volatile("cp.async.cg.shared.global [%0], [%1], 16, %2;"
                 :: "r"(dst), "l"(src), "r"(srcsize) : "memory");
}

__device__ __forceinline__ void mma16816(float* d, const uint32_t* a, const uint32_t* b) {
    asm volatile(
        "mma.sync.aligned.m16n8k16.row.col.f32.f16.f16.f32 "
        "{%0,%1,%2,%3}, {%4,%5,%6,%7}, {%8,%9}, {%0,%1,%2,%3};"
        : "+f"(d[0]), "+f"(d[1]), "+f"(d[2]), "+f"(d[3])
        : "r"(a[0]), "r"(a[1]), "r"(a[2]), "r"(a[3]), "r"(b[0]), "r"(b[1]));
}

// ---- packed fp32x2 (FFMA2) helpers ----
__device__ __forceinline__ uint64_t pk2(float x) {
    uint64_t r;
    asm("mov.b64 %0, {%1, %1};" : "=l"(r) : "f"(x));
    return r;
}
__device__ __forceinline__ void fma2(uint64_t &d, uint64_t a, uint64_t b) {
    asm("fma.rn.f32x2 %0, %1, %2, %0;" : "+l"(d) : "l"(a), "l"(b));
}
__device__ __forceinline__ float2 up2(uint64_t v) {
    float2 r;
    asm("mov.b64 {%0, %1}, %2;" : "=f"(r.x), "=f"(r.y) : "l"(v));
    return r;
}

// ---------------- fp16 tensor-core GEMM, 3-stage cp.async pipeline (NT) ----------------
// __launch_bounds__(256,2): cap regs at 124 so 2 CTAs/SM fit the regfile.
__global__ __launch_bounds__(256, 2) void hgemm_nt_kernel(
    const __half* __restrict__ A, const __half* __restrict__ B, float* __restrict__ C,
    int M, int N, int K)
{
    __shared__ __align__(16) __half As[3][128][40];
    __shared__ __align__(16) __half Bs[3][128][40];

    const int tid  = threadIdx.x;
    const int warp = tid >> 5;
    const int lane = tid & 31;
    const int g    = lane >> 2;
    const int t4   = lane & 3;
    const int wm   = (warp >> 1) * 32;
    const int wn   = (warp & 1) * 64;
    const int m0   = blockIdx.y * 128;
    const int n0   = blockIdx.x * 128;

    const int lm  = lane >> 3;
    const int lr  = lane & 7;
    const int arow = (lm & 1) * 8 + lr;
    const int acol = (lm >> 1) * 8;
    const int brow = (lm >> 1) * 8 + lr;
    const int bcol = (lm & 1) * 8;

    const uint32_t as_b = smem_u32(&As[0][0][0]);
    const uint32_t bs_b = smem_u32(&Bs[0][0][0]);
    const uint32_t BUFB = 128u * 40u * 2u;

    float d[2][8][4];
#pragma unroll
    for (int i = 0; i < 2; i++)
#pragma unroll
        for (int j = 0; j < 8; j++)
#pragma unroll
            for (int v = 0; v < 4; v++) d[i][j][v] = 0.0f;

    const int nch = K >> 5;

    auto stage = [&](int kc, int buf) {
        const int kb = kc << 5;
#pragma unroll
        for (int i = 0; i < 2; i++) {
            const int f   = tid + (i << 8);
            const int row = f >> 2;
            const int seg = f & 3;
            const uint32_t off = (uint32_t)(row * 80 + seg * 16);
            cp_async16(as_b + (uint32_t)buf * BUFB + off,
                       &A[(size_t)(m0 + row) * K + kb + seg * 8], 16);
            const int nr = n0 + row;
            const int ok = (nr < N);
            cp_async16(bs_b + (uint32_t)buf * BUFB + off,
                       &B[(size_t)(ok ? nr : 0) * K + kb + seg * 8], ok ? 16 : 0);
        }
        asm volatile("cp.async.commit_group;" ::: "memory");
    };

    stage(0, 0);
    if (nch > 1) stage(1, 1);

    for (int kc = 0; kc < nch; kc++) {
        const int buf = kc % 3;
        if (kc + 1 < nch) {
            asm volatile("cp.async.wait_group 1;" ::: "memory");
        } else {
            asm volatile("cp.async.wait_group 0;" ::: "memory");
        }
        __syncthreads();
        if (kc + 2 < nch) stage(kc + 2, (kc + 2) % 3);

        const uint32_t ab = as_b + (uint32_t)buf * BUFB;
        const uint32_t bb = bs_b + (uint32_t)buf * BUFB;
#pragma unroll
        for (int s = 0; s < 2; s++) {
            const int kk = s * 16;
            uint32_t af[2][4];
#pragma unroll
            for (int mt = 0; mt < 2; mt++) {
                uint32_t addr = ab + (uint32_t)(((wm + mt * 16 + arow) * 40 + kk + acol) * 2);
                ldsm4(af[mt][0], af[mt][1], af[mt][2], af[mt][3], addr);
            }
            uint32_t bf[8][2];
#pragma unroll
            for (int ntp = 0; ntp < 4; ntp++) {
                uint32_t q0, q1, q2, q3;
                uint32_t addr = bb + (uint32_t)(((wn + ntp * 16 + brow) * 40 + kk + bcol) * 2);
                ldsm4(q0, q1, q2, q3, addr);
                bf[2 * ntp][0]     = q0;  bf[2 * ntp][1]     = q1;
                bf[2 * ntp + 1][0] = q2;  bf[2 * ntp + 1][1] = q3;
            }
#pragma unroll
            for (int mt = 0; mt < 2; mt++) {
#pragma unroll
                for (int nt = 0; nt < 8; nt++) {
                    mma16816(d[mt][nt], af[mt], bf[nt]);
                }
            }
        }
    }

#pragma unroll
    for (int mt = 0; mt < 2; mt++) {
        const int mrow = m0 + wm + mt * 16;
#pragma unroll
        for (int nt = 0; nt < 8; nt++) {
            const int ncol = n0 + wn + nt * 8 + t4 * 2;
            if (ncol < N) {
                *(float2*)&C[(size_t)(mrow + g    ) * N + ncol] =
                    make_float2(d[mt][nt][0], d[mt][nt][1]);
                *(float2*)&C[(size_t)(mrow + g + 8) * N + ncol] =
                    make_float2(d[mt][nt][2], d[mt][nt][3]);
            }
        }
    }
}

// ---------------- fp32 -> fp16 conversion (vectorized) ----------------
__global__ __launch_bounds__(256) void f2h_kernel(const float* __restrict__ src,
                                                  __half* __restrict__ dst, size_t n)
{
    size_t i = ((size_t)blockIdx.x * blockDim.x + threadIdx.x) * 4;
    if (i >= n) return;
    float4 v = *(const float4*)&src[i];
    __half2* d2 = (__half2*)&dst[i];
    d2[0] = __floats2half2_rn(v.x, v.y);
    d2[1] = __floats2half2_rn(v.z, v.w);
}

// ---------------- conv1d (width 4, causal) + bias + SiLU ----------------
__global__ __launch_bounds__(256) void conv_silu_kernel(
    const float* __restrict__ conv_w, const float* __restrict__ conv_b)
{
    size_t idx = (size_t)blockIdx.x * blockDim.x + threadIdx.x;
    if (idx >= (size_t)ROWS * CONVDIM) return;
    int c = (int)(idx % CONVDIM);
    size_t bt = idx / CONVDIM;
    int t = (int)(bt % LL);
    size_t brow0 = (bt - t);

    float accv = conv_b[c];
#pragma unroll
    for (int w = 0; w < DCONV; w++) {
        int ts = t - (DCONV - 1) + w;
        if (ts >= 0) {
            accv = fmaf(g_zxbcdt[(brow0 + ts) * (size_t)DPROJ + DSSM + c],
                        conv_w[c * DCONV + w], accv);
        }
    }
    g_xbc[idx] = silu_f(accv);
}

// ---------------- dt softplus + log-decay (transposed layouts) ----------------
__global__ __launch_bounds__(256) void dt_kernel(
    const float* __restrict__ dt_bias, const float* __restrict__ A_log)
{
    int idx = blockIdx.x * blockDim.x + threadIdx.x;
    if (idx >= ROWS * NH) return;
    int h = idx % NH;
    int r = idx / NH;
    float raw = g_zxbcdt[(size_t)r * DPROJ + DSSM + CONVDIM + h] + dt_bias[h];
    float dt = (raw > 20.0f) ? raw : log1pf(expf(raw));
    float Aneg = -expf(A_log[h]);
    g_dtT[(size_t)h * ROWS + r] = dt;
    g_ldAT[(size_t)h * ROWS + r] = dt * Aneg;
}

// ================= Chunked SSD scan =================

// ---------------- Phase A: per-chunk state increment (fp32, FFMA2 packed) ----------------
__global__ __launch_bounds__(256) void ssd_phaseA_kernel()
{
    extern __shared__ float sm[];
    float* s_B    = sm;                    // [64][132]
    float* s_wdtx = sm + 64 * 132;         // [64][68]
    float* s_w    = s_wdtx + 64 * 68;      // [64]
    float* s_cl   = s_w + 64;              // [64]

    const int tid = threadIdx.x;
    const int bx  = blockIdx.x;
    const int c   = bx & (NCHUNK - 1);
    const int bh  = bx >> 6;
    const int b   = bh >> 5;
    const int h   = bh & 31;
    const int t0row = b * LL + c * CT;

    if (tid == 0) {
        float cl = 0.f;
        const float* ld = g_ldAT + (size_t)h * ROWS + t0row;
#pragma unroll 4
        for (int t = 0; t < CT; t++) { cl += ld[t]; s_cl[t] = cl; }
    }
#pragma unroll
    for (int i = 0; i < 8; i++) {
        const int f = tid + (i << 8);
        const int row = f >> 5;
        const int q = (f & 31) << 2;
        float4 v = *(const float4*)&g_xbc[(size_t)(t0row + row) * CONVDIM + DSSM + q];
        *(float4*)&s_B[row * 132 + q] = v;
    }
    __syncthreads();

    const float cend = s_cl[CT - 1];
    if (tid < CT) {
        s_w[tid] = expf(cend - s_cl[tid]);
        g_cumlog[(size_t)bx * CT + tid] = s_cl[tid];
        if (tid == 0) g_clend[bx] = cend;
    }
    __syncthreads();

#pragma unroll
    for (int i = 0; i < 16; i++) {
        const int f = tid + (i << 8);
        const int tau = f & 63;
        const int p = f >> 6;
        const float dt = g_dtT[(size_t)h * ROWS + t0row + tau];
        const float xv = g_xbc[(size_t)(t0row + tau) * CONVDIM + h * HD + p];
        s_wdtx[tau * 68 + p] = s_w[tau] * dt * xv;
    }
    __syncthreads();

    const int pp = tid >> 4;
    const int nu = tid & 15;
    const int p0 = pp << 2;
    const int n0 = nu << 3;
    uint64_t accp[4][4];
#pragma unroll
    for (int i = 0; i < 4; i++)
#pragma unroll
        for (int j = 0; j < 4; j++) accp[i][j] = 0ull;

#pragma unroll 4
    for (int t4_ = 0; t4_ < 16; t4_++) {
        const int tau = t4_ << 2;
        float4 wv[4];
        ulonglong2 bq[4][2];
#pragma unroll
        for (int k = 0; k < 4; k++) {
            wv[k] = *(const float4*)&s_wdtx[(tau + k) * 68 + p0];
            bq[k][0] = *(const ulonglong2*)&s_B[(tau + k) * 132 + n0];
            bq[k][1] = *(const ulonglong2*)&s_B[(tau + k) * 132 + n0 + 4];
        }
#pragma unroll
        for (int k = 0; k < 4; k++) {
            const float* wp = (const float*)&wv[k];
#pragma unroll
            for (int i = 0; i < 4; i++) {
                const uint64_t s = pk2(wp[i]);
                fma2(accp[i][0], s, bq[k][0].x);
                fma2(accp[i][1], s, bq[k][0].y);
                fma2(accp[i][2], s, bq[k][1].x);
                fma2(accp[i][3], s, bq[k][1].y);
            }
        }
    }
    float* dh = g_dH + (size_t)bx * (HD * DSTATE);
#pragma unroll
    for (int i = 0; i < 4; i++) {
        ulonglong2 s0; s0.x = accp[i][0]; s0.y = accp[i][1];
        ulonglong2 s1; s1.x = accp[i][2]; s1.y = accp[i][3];
        *(ulonglong2*)&dh[(p0 + i) * DSTATE + n0]     = s0;
        *(ulonglong2*)&dh[(p0 + i) * DSTATE + n0 + 4] = s1;
    }
}

// ---------------- Phase B: chunk-level recurrence (parallel over state) ----------------
__global__ __launch_bounds__(256) void ssd_phaseB_kernel()
{
    const int gid = blockIdx.x * 256 + threadIdx.x;
    const int bh  = gid >> 11;
    const int e   = (gid & 2047) << 2;

    float4 h = make_float4(0.f, 0.f, 0.f, 0.f);
    const size_t sbase = (size_t)bh * NCHUNK;
    for (int c = 0; c < NCHUNK; c++) {
        const size_t slot = sbase + c;
        const float4 d4 = *(const float4*)&g_dH[slot * (HD * DSTATE) + e];
        *(float4*)&g_hpre[slot * (HD * DSTATE) + e] = h;
        const float P = expf(g_clend[slot]);
        h.x = fmaf(h.x, P, d4.x);
        h.y = fmaf(h.y, P, d4.y);
        h.z = fmaf(h.z, P, d4.z);
        h.w = fmaf(h.w, P, d4.w);
    }
}

// ---------------- Phase C: per-chunk output (fp32, FFMA2; G+Y2 fused pass) ----------------
__global__ __launch_bounds__(256) void ssd_phaseC_kernel(const float* __restrict__ Dp)
{
    extern __shared__ float sm[];
    float* s_C   = sm;                       // [64][132]
    float* s_BT  = s_C + 64 * 132;           // [128][68]
    float* s_hT  = s_BT + 128 * 68;          // [128][68]
    float* s_dtx = s_hT + 128 * 68;          // [64][68]
    float* s_Gm  = s_dtx + 64 * 68;          // [64][68]
    float* s_cl  = s_Gm + 64 * 68;           // [64]

    const int tid = threadIdx.x;
    const int bx  = blockIdx.x;
    const int c   = bx & (NCHUNK - 1);
    const int bh  = bx >> 6;
    const int b   = bh >> 5;
    const int h   = bh & 31;
    const int t0row = b * LL + c * CT;
    const float Dh = Dp[h];

#pragma unroll
    for (int i = 0; i < 8; i++) {
        const int f = tid + (i << 8);
        const int row = f >> 5;
        const int q = (f & 31) << 2;
        float4 cv = *(const float4*)&g_xbc[(size_t)(t0row + row) * CONVDIM + DSSM + DSTATE + q];
        *(float4*)&s_C[row * 132 + q] = cv;
        float4 bv = *(const float4*)&g_xbc[(size_t)(t0row + row) * CONVDIM + DSSM + q];
        s_BT[(q + 0) * 68 + row] = bv.x;
        s_BT[(q + 1) * 68 + row] = bv.y;
        s_BT[(q + 2) * 68 + row] = bv.z;
        s_BT[(q + 3) * 68 + row] = bv.w;
        const int p = f >> 5;
        float4 hv = *(const float4*)&g_hpre[(size_t)bx * (HD * DSTATE) + p * DSTATE + q];
        s_hT[(q + 0) * 68 + p] = hv.x;
        s_hT[(q + 1) * 68 + p] = hv.y;
        s_hT[(q + 2) * 68 + p] = hv.z;
        s_hT[(q + 3) * 68 + p] = hv.w;
    }
#pragma unroll
    for (int i = 0; i < 16; i++) {
        const int f = tid + (i << 8);
        const int tau = f & 63;
        const int p = f >> 6;
        const float dt = g_dtT[(size_t)h * ROWS + t0row + tau];
        const float xv = g_xbc[(size_t)(t0row + tau) * CONVDIM + h * HD + p];
        s_dtx[tau * 68 + p] = dt * xv;
    }
    if (tid < CT) s_cl[tid] = g_cumlog[(size_t)bx * CT + tid];
    __syncthreads();

    const int tt = tid >> 4;
    const int tu = tid & 15;
    const int t0 = tt << 2;
    const int u0 = tu << 2;     // == p0: same column base for G (u) and Y2 (p)

    uint64_t y2[4][2];
#pragma unroll
    for (int i = 0; i < 4; i++) { y2[i][0] = 0ull; y2[i][1] = 0ull; }

    // ---- fused pass: G = C @ B^T  AND  Y2 = C @ h^T (shared cv loads) ----
    {
        uint64_t gp[4][2];
#pragma unroll
        for (int i = 0; i < 4; i++) { gp[i][0] = 0ull; gp[i][1] = 0ull; }
#pragma unroll 2
        for (int n4 = 0; n4 < 32; n4++) {
            const int n = n4 << 2;
            float4 cv[4];
            ulonglong2 bq[4], hq[4];
#pragma unroll
            for (int i = 0; i < 4; i++) cv[i] = *(const float4*)&s_C[(t0 + i) * 132 + n];
#pragma unroll
            for (int k = 0; k < 4; k++) {
                bq[k] = *(const ulonglong2*)&s_BT[(n + k) * 68 + u0];
                hq[k] = *(const ulonglong2*)&s_hT[(n + k) * 68 + u0];
            }
#pragma unroll
            for (int k = 0; k < 4; k++) {
#pragma unroll
                for (int i = 0; i < 4; i++) {
                    const uint64_t s = pk2(((const float*)&cv[i])[k]);
                    fma2(gp[i][0], s, bq[k].x);
                    fma2(gp[i][1], s, bq[k].y);
                    fma2(y2[i][0], s, hq[k].x);
                    fma2(y2[i][1], s, hq[k].y);
                }
            }
        }
        // mask + decay, write Gm
#pragma unroll
        for (int i = 0; i < 4; i++) {
            const int t = t0 + i;
            const float clt = s_cl[t];
            const float2 a01 = up2(gp[i][0]);
            const float2 a23 = up2(gp[i][1]);
            const float av[4] = {a01.x, a01.y, a23.x, a23.y};
#pragma unroll
            for (int j = 0; j < 4; j++) {
                const int u = u0 + j;
                s_Gm[t * 68 + u] = (u <= t) ? expf(clt - s_cl[u]) * av[j] : 0.f;
            }
        }
    }
    __syncthreads();

    // ---- Y1 = Gm @ dtx; combine with Y2, D*x epilogue ----
    {
        const int p0 = tu << 2;
        uint64_t y1[4][2];
#pragma unroll
        for (int i = 0; i < 4; i++) { y1[i][0] = 0ull; y1[i][1] = 0ull; }

#pragma unroll 4
        for (int u4 = 0; u4 < 16; u4++) {
            const int u = u4 << 2;
            float4 gv[4];
            ulonglong2 dq[4];
#pragma unroll
            for (int i = 0; i < 4; i++) gv[i] = *(const float4*)&s_Gm[(t0 + i) * 68 + u];
#pragma unroll
            for (int k = 0; k < 4; k++) dq[k] = *(const ulonglong2*)&s_dtx[(u + k) * 68 + p0];
#pragma unroll
            for (int k = 0; k < 4; k++) {
#pragma unroll
                for (int i = 0; i < 4; i++) {
                    const uint64_t s = pk2(((const float*)&gv[i])[k]);
                    fma2(y1[i][0], s, dq[k].x);
                    fma2(y1[i][1], s, dq[k].y);
                }
            }
        }
#pragma unroll
        for (int i = 0; i < 4; i++) {
            const int t = t0 + i;
            const int row = t0row + t;
            const float et = expf(s_cl[t]);
            const float2 a01 = up2(y1[i][0]);
            const float2 a23 = up2(y1[i][1]);
            const float2 b01 = up2(y2[i][0]);
            const float2 b23 = up2(y2[i][1]);
            float4 xv = *(const float4*)&g_xbc[(size_t)row * CONVDIM + h * HD + p0];
            float4 y4;
            y4.x = fmaf(et, b01.x, a01.x) + Dh * xv.x;
            y4.y = fmaf(et, b01.y, a01.y) + Dh * xv.y;
            y4.z = fmaf(et, b23.x, a23.x) + Dh * xv.z;
            y4.w = fmaf(et, b23.y, a23.y) + Dh * xv.w;
            *(float4*)&g_y[(size_t)row * DSSM + h * HD + p0] = y4;
        }
    }
}

// ---------------- gate (silu(z)) + RMSNorm -> fp16 output for GEMM2 ----------------
__global__ __launch_bounds__(256) void gate_rmsnorm_kernel(const float* __restrict__ norm_w)
{
    const int row = blockIdx.x;
    const int tid = threadIdx.x;
    const int w = tid >> 5, lane = tid & 31;

    float vals[8];
    float ss = 0.f;
#pragma unroll
    for (int i = 0; i < 8; i++) {
        int e = i * 256 + tid;
        float z = g_zxbcdt[(size_t)row * DPROJ + e];
        float yv = g_y[(size_t)row * DSSM + e];
        float g = yv * silu_f(z);
        vals[i] = g;
        ss = fmaf(g, g, ss);
    }
    ss += __shfl_xor_sync(0xffffffffu, ss, 16);
    ss += __shfl_xor_sync(0xffffffffu, ss, 8);
    ss += __shfl_xor_sync(0xffffffffu, ss, 4);
    ss += __shfl_xor_sync(0xffffffffu, ss, 2);
    ss += __shfl_xor_sync(0xffffffffu, ss, 1);

    __shared__ float red[8];
    __shared__ float sscale;
    if (lane == 0) red[w] = ss;
    __syncthreads();
    if (tid == 0) {
        float s = 0.f;
#pragma unroll
        for (int k = 0; k < 8; k++) s += red[k];
        sscale = rsqrtf(s / (float)DSSM + EPSV);
    }
    __syncthreads();
    const float scale = sscale;
#pragma unroll
    for (int i = 0; i < 8; i++) {
        int e = i * 256 + tid;
        g_gh[(size_t)row * DSSM + e] = __float2half(vals[i] * scale * norm_w[e]);
    }
}

// ---------------- entry ----------------
extern "C" void kernel_launch(void* const* d_in, const int* in_sizes, int n_in,
                              void* d_out, int out_size)
{
    const float* u       = (const float*)d_in[0];
    const float* W_in    = (const float*)d_in[1];
    const float* conv_w  = (const float*)d_in[2];
    const float* conv_b  = (const float*)d_in[3];
    const float* dt_bias = (const float*)d_in[4];
    const float* A_log   = (const float*)d_in[5];
    const float* Dp      = (const float*)d_in[6];
    const float* norm_w  = (const float*)d_in[7];
    const float* W_out   = (const float*)d_in[8];
    float* out = (float*)d_out;

    float*  zx;  cudaGetSymbolAddress((void**)&zx,  g_zxbcdt);
    __half* uh;  cudaGetSymbolAddress((void**)&uh,  g_uh);
    __half* wih; cudaGetSymbolAddress((void**)&wih, g_Winh);
    __half* gh;  cudaGetSymbolAddress((void**)&gh,  g_gh);
    __half* woh; cudaGetSymbolAddress((void**)&woh, g_Wouth);

    const int smA = (64 * 132 + 64 * 68 + 64 + 64) * 4;
    const int smC = (64 * 132 + 128 * 68 + 128 * 68 + 64 * 68 + 64 * 68 + 64) * 4;
    cudaFuncSetAttribute(ssd_phaseA_kernel, cudaFuncAttributeMaxDynamicSharedMemorySize, smA);
    cudaFuncSetAttribute(ssd_phaseC_kernel, cudaFuncAttributeMaxDynamicSharedMemorySize, smC);

    // 0) fp16 conversions
    {
        size_t nu = (size_t)ROWS * DMODEL;
        f2h_kernel<<<(unsigned)((nu / 4 + 255) / 256), 256>>>(u, uh, nu);
        size_t nw = (size_t)DPROJ * DMODEL;
        f2h_kernel<<<(unsigned)((nw / 4 + 255) / 256), 256>>>(W_in, wih, nw);
        size_t no = (size_t)DMODEL * DSSM;
        f2h_kernel<<<(unsigned)((no / 4 + 255) / 256), 256>>>(W_out, woh, no);
    }
    // 1) in-projection
    {
        dim3 grid((DPROJ + 127) / 128, ROWS / 128);
        hgemm_nt_kernel<<<grid, 256>>>(uh, wih, zx, ROWS, DPROJ, DMODEL);
    }
    // 2) conv + silu
    {
        size_t total = (size_t)ROWS * CONVDIM;
        conv_silu_kernel<<<(unsigned)((total + 255) / 256), 256>>>(conv_w, conv_b);
    }
    // 3) dt softplus + log decay
    dt_kernel<<<(ROWS * NH + 255) / 256, 256>>>(dt_bias, A_log);
    // 4) chunked SSD scan
    ssd_phaseA_kernel<<<NSLOT, 256, smA>>>();
    ssd_phaseB_kernel<<<512, 256>>>();
    ssd_phaseC_kernel<<<NSLOT, 256, smC>>>(Dp);
    // 5) gate + rmsnorm
    gate_rmsnorm_kernel<<<ROWS, 256>>>(norm_w);
    // 6) out-projection
    {
        dim3 grid(DMODEL / 128, ROWS / 128);
        hgemm_nt_kernel<<<grid, 256>>>(gh, woh, out, ROWS, DMODEL, DSSM);
    }
}

// round 14
// speedup vs baseline: 1.1854x; 1.0694x over previous
#include <cuda_runtime.h>
#include <cuda_fp16.h>
#include <math.h>
#include <stdint.h>

// ---------------- Problem constants ----------------
#define BB      2
#define LL      4096
#define DMODEL  1024
#define DSSM    2048
#define DSTATE  128
#define DCONV   4
#define NH      32
#define HD      64
#define CONVDIM (DSSM + 2*DSTATE)          // 2304
#define DPROJ   (2*DSSM + 2*DSTATE + NH)   // 4384
#define EPSV    1e-5f

#define ROWS    (BB*LL)                    // 8192
#define CT      64                         // chunk length
#define NCHUNK  (LL/CT)                    // 64
#define NSLOT   (BB*NH*NCHUNK)             // 4096

// ---------------- Scratch (static device arrays; no allocation) ----------------
__device__ float  g_zxbcdt[(size_t)ROWS * DPROJ];
__device__ float  g_xbc[(size_t)ROWS * CONVDIM];
__device__ float  g_dtT[(size_t)NH * ROWS];
__device__ float  g_ldAT[(size_t)NH * ROWS];
__device__ float  g_y[(size_t)ROWS * DSSM];
__device__ float  g_dH[(size_t)NSLOT * HD * DSTATE];
__device__ float  g_hpre[(size_t)NSLOT * HD * DSTATE];
__device__ float  g_cumlog[(size_t)NSLOT * CT];
__device__ float  g_clend[NSLOT];
__device__ __half g_uh[(size_t)ROWS * DMODEL];
__device__ __half g_Winh[(size_t)DPROJ * DMODEL];
__device__ __half g_gh[(size_t)ROWS * DSSM];
__device__ __half g_Wouth[(size_t)DMODEL * DSSM];

// ---------------- helpers ----------------
__device__ __forceinline__ float silu_f(float x) {
    return x / (1.0f + expf(-x));
}

__device__ __forceinline__ uint32_t smem_u32(const void* p) {
    uint32_t a;
    asm("{ .reg .u64 t; cvta.to.shared.u64 t, %1; cvt.u32.u64 %0, t; }" : "=r"(a) : "l"(p));
    return a;
}

__device__ __forceinline__ void ldsm4(uint32_t &r0, uint32_t &r1, uint32_t &r2, uint32_t &r3,
                                      uint32_t saddr) {
    asm volatile("ldmatrix.sync.aligned.m8n8.x4.shared.b16 {%0,%1,%2,%3}, [%4];"
                 : "=r"(r0), "=r"(r1), "=r"(r2), "=r"(r3)
                 : "r"(saddr));
}

__device__ __forceinline__ void cp_async16(uint32_t dst, const void* src, int srcsize) {
    asm volatile("cp.async.cg.shared.global [%0], [%1], 16, %2;"
                 :: "r"(dst), "l"(src), "r"(srcsize) : "memory");
}

__device__ __forceinline__ void mma16816(float* d, const uint32_t* a, const uint32_t* b) {
    asm volatile(
        "mma.sync.aligned.m16n8k16.row.col.f32.f16.f16.f32 "
        "{%0,%1,%2,%3}, {%4,%5,%6,%7}, {%8,%9}, {%0,%1,%2,%3};"
        : "+f"(d[0]), "+f"(d[1]), "+f"(d[2]), "+f"(d[3])
        : "r"(a[0]), "r"(a[1]), "r"(a[2]), "r"(a[3]), "r"(b[0]), "r"(b[1]));
}

// ---- packed fp32x2 (FFMA2) helpers ----
__device__ __forceinline__ uint64_t pk2(float x) {
    uint64_t r;
    asm("mov.b64 %0, {%1, %1};" : "=l"(r) : "f"(x));
    return r;
}
__device__ __forceinline__ void fma2(uint64_t &d, uint64_t a, uint64_t b) {
    asm("fma.rn.f32x2 %0, %1, %2, %0;" : "+l"(d) : "l"(a), "l"(b));
}
__device__ __forceinline__ float2 up2(uint64_t v) {
    float2 r;
    asm("mov.b64 {%0, %1}, %2;" : "=f"(r.x), "=f"(r.y) : "l"(v));
    return r;
}

// ---------------- fp16 tensor-core GEMM, 3-stage cp.async pipeline (NT) ----------------
__global__ __launch_bounds__(256, 2) void hgemm_nt_kernel(
    const __half* __restrict__ A, const __half* __restrict__ B, float* __restrict__ C,
    int M, int N, int K)
{
    __shared__ __align__(16) __half As[3][128][40];
    __shared__ __align__(16) __half Bs[3][128][40];

    const int tid  = threadIdx.x;
    const int warp = tid >> 5;
    const int lane = tid & 31;
    const int g    = lane >> 2;
    const int t4   = lane & 3;
    const int wm   = (warp >> 1) * 32;
    const int wn   = (warp & 1) * 64;
    const int m0   = blockIdx.y * 128;
    const int n0   = blockIdx.x * 128;

    const int lm  = lane >> 3;
    const int lr  = lane & 7;
    const int arow = (lm & 1) * 8 + lr;
    const int acol = (lm >> 1) * 8;
    const int brow = (lm >> 1) * 8 + lr;
    const int bcol = (lm & 1) * 8;

    const uint32_t as_b = smem_u32(&As[0][0][0]);
    const uint32_t bs_b = smem_u32(&Bs[0][0][0]);
    const uint32_t BUFB = 128u * 40u * 2u;

    float d[2][8][4];
#pragma unroll
    for (int i = 0; i < 2; i++)
#pragma unroll
        for (int j = 0; j < 8; j++)
#pragma unroll
            for (int v = 0; v < 4; v++) d[i][j][v] = 0.0f;

    const int nch = K >> 5;

    auto stage = [&](int kc, int buf) {
        const int kb = kc << 5;
#pragma unroll
        for (int i = 0; i < 2; i++) {
            const int f   = tid + (i << 8);
            const int row = f >> 2;
            const int seg = f & 3;
            const uint32_t off = (uint32_t)(row * 80 + seg * 16);
            cp_async16(as_b + (uint32_t)buf * BUFB + off,
                       &A[(size_t)(m0 + row) * K + kb + seg * 8], 16);
            const int nr = n0 + row;
            const int ok = (nr < N);
            cp_async16(bs_b + (uint32_t)buf * BUFB + off,
                       &B[(size_t)(ok ? nr : 0) * K + kb + seg * 8], ok ? 16 : 0);
        }
        asm volatile("cp.async.commit_group;" ::: "memory");
    };

    stage(0, 0);
    if (nch > 1) stage(1, 1);

    for (int kc = 0; kc < nch; kc++) {
        const int buf = kc % 3;
        if (kc + 1 < nch) {
            asm volatile("cp.async.wait_group 1;" ::: "memory");
        } else {
            asm volatile("cp.async.wait_group 0;" ::: "memory");
        }
        __syncthreads();
        if (kc + 2 < nch) stage(kc + 2, (kc + 2) % 3);

        const uint32_t ab = as_b + (uint32_t)buf * BUFB;
        const uint32_t bb = bs_b + (uint32_t)buf * BUFB;
#pragma unroll
        for (int s = 0; s < 2; s++) {
            const int kk = s * 16;
            uint32_t af[2][4];
#pragma unroll
            for (int mt = 0; mt < 2; mt++) {
                uint32_t addr = ab + (uint32_t)(((wm + mt * 16 + arow) * 40 + kk + acol) * 2);
                ldsm4(af[mt][0], af[mt][1], af[mt][2], af[mt][3], addr);
            }
            uint32_t bf[8][2];
#pragma unroll
            for (int ntp = 0; ntp < 4; ntp++) {
                uint32_t q0, q1, q2, q3;
                uint32_t addr = bb + (uint32_t)(((wn + ntp * 16 + brow) * 40 + kk + bcol) * 2);
                ldsm4(q0, q1, q2, q3, addr);
                bf[2 * ntp][0]     = q0;  bf[2 * ntp][1]     = q1;
                bf[2 * ntp + 1][0] = q2;  bf[2 * ntp + 1][1] = q3;
            }
#pragma unroll
            for (int mt = 0; mt < 2; mt++) {
#pragma unroll
                for (int nt = 0; nt < 8; nt++) {
                    mma16816(d[mt][nt], af[mt], bf[nt]);
                }
            }
        }
    }

#pragma unroll
    for (int mt = 0; mt < 2; mt++) {
        const int mrow = m0 + wm + mt * 16;
#pragma unroll
        for (int nt = 0; nt < 8; nt++) {
            const int ncol = n0 + wn + nt * 8 + t4 * 2;
            if (ncol < N) {
                *(float2*)&C[(size_t)(mrow + g    ) * N + ncol] =
                    make_float2(d[mt][nt][0], d[mt][nt][1]);
                *(float2*)&C[(size_t)(mrow + g + 8) * N + ncol] =
                    make_float2(d[mt][nt][2], d[mt][nt][3]);
            }
        }
    }
}

// ---------------- fp32 -> fp16 conversion (vectorized) ----------------
__global__ __launch_bounds__(256) void f2h_kernel(const float* __restrict__ src,
                                                  __half* __restrict__ dst, size_t n)
{
    size_t i = ((size_t)blockIdx.x * blockDim.x + threadIdx.x) * 4;
    if (i >= n) return;
    float4 v = *(const float4*)&src[i];
    __half2* d2 = (__half2*)&dst[i];
    d2[0] = __floats2half2_rn(v.x, v.y);
    d2[1] = __floats2half2_rn(v.z, v.w);
}

// ---------------- conv1d (width 4, causal) + bias + SiLU: 4 t's per thread ----------------
__global__ __launch_bounds__(256) void conv_silu_kernel(
    const float* __restrict__ conv_w, const float* __restrict__ conv_b)
{
    const int TB = LL / 4;                                  // 1024 t-blocks per batch
    int idx = blockIdx.x * 256 + threadIdx.x;
    if (idx >= BB * TB * CONVDIM) return;
    const int c  = idx % CONVDIM;
    const int tb = idx / CONVDIM;
    const int t0 = (tb % TB) * 4;
    const int b  = tb / TB;

    const float w0 = conv_w[c * DCONV + 0];
    const float w1 = conv_w[c * DCONV + 1];
    const float w2 = conv_w[c * DCONV + 2];
    const float w3 = conv_w[c * DCONV + 3];
    const float bias = conv_b[c];

    const size_t base = (size_t)(b * LL) * DPROJ + DSSM + c;
    float x[7];
#pragma unroll
    for (int j = 0; j < 7; j++) {
        const int ts = t0 - 3 + j;
        x[j] = (ts >= 0) ? g_zxbcdt[base + (size_t)ts * DPROJ] : 0.0f;
    }
#pragma unroll
    for (int k = 0; k < 4; k++) {
        float acc = bias;
        acc = fmaf(x[k + 0], w0, acc);
        acc = fmaf(x[k + 1], w1, acc);
        acc = fmaf(x[k + 2], w2, acc);
        acc = fmaf(x[k + 3], w3, acc);
        g_xbc[(size_t)(b * LL + t0 + k) * CONVDIM + c] = silu_f(acc);
    }
}

// ---------------- dt softplus + log-decay (transposed layouts) ----------------
__global__ __launch_bounds__(256) void dt_kernel(
    const float* __restrict__ dt_bias, const float* __restrict__ A_log)
{
    int idx = blockIdx.x * blockDim.x + threadIdx.x;
    if (idx >= ROWS * NH) return;
    int h = idx % NH;
    int r = idx / NH;
    float raw = g_zxbcdt[(size_t)r * DPROJ + DSSM + CONVDIM + h] + dt_bias[h];
    float dt = (raw > 20.0f) ? raw : log1pf(expf(raw));
    float Aneg = -expf(A_log[h]);
    g_dtT[(size_t)h * ROWS + r] = dt;
    g_ldAT[(size_t)h * ROWS + r] = dt * Aneg;
}

// ================= Chunked SSD scan =================

// ---------------- Phase A: per-chunk state increment (fp32, FFMA2 packed) ----------------
__global__ __launch_bounds__(256) void ssd_phaseA_kernel()
{
    extern __shared__ float sm[];
    float* s_B    = sm;                    // [64][132]
    float* s_wdtx = sm + 64 * 132;         // [64][68]
    float* s_w    = s_wdtx + 64 * 68;      // [64]
    float* s_cl   = s_w + 64;              // [64]

    const int tid = threadIdx.x;
    const int bx  = blockIdx.x;
    const int c   = bx & (NCHUNK - 1);
    const int bh  = bx >> 6;
    const int b   = bh >> 5;
    const int h   = bh & 31;
    const int t0row = b * LL + c * CT;

    if (tid == 0) {
        float cl = 0.f;
        const float* ld = g_ldAT + (size_t)h * ROWS + t0row;
#pragma unroll 4
        for (int t = 0; t < CT; t++) { cl += ld[t]; s_cl[t] = cl; }
    }
#pragma unroll
    for (int i = 0; i < 8; i++) {
        const int f = tid + (i << 8);
        const int row = f >> 5;
        const int q = (f & 31) << 2;
        float4 v = *(const float4*)&g_xbc[(size_t)(t0row + row) * CONVDIM + DSSM + q];
        *(float4*)&s_B[row * 132 + q] = v;
    }
    __syncthreads();

    const float cend = s_cl[CT - 1];
    if (tid < CT) {
        s_w[tid] = expf(cend - s_cl[tid]);
        g_cumlog[(size_t)bx * CT + tid] = s_cl[tid];
        if (tid == 0) g_clend[bx] = cend;
    }
    __syncthreads();

#pragma unroll
    for (int i = 0; i < 16; i++) {
        const int f = tid + (i << 8);
        const int tau = f & 63;
        const int p = f >> 6;
        const float dt = g_dtT[(size_t)h * ROWS + t0row + tau];
        const float xv = g_xbc[(size_t)(t0row + tau) * CONVDIM + h * HD + p];
        s_wdtx[tau * 68 + p] = s_w[tau] * dt * xv;
    }
    __syncthreads();

    const int pp = tid >> 4;
    const int nu = tid & 15;
    const int p0 = pp << 2;
    const int n0 = nu << 3;
    uint64_t accp[4][4];
#pragma unroll
    for (int i = 0; i < 4; i++)
#pragma unroll
        for (int j = 0; j < 4; j++) accp[i][j] = 0ull;

#pragma unroll 4
    for (int t4_ = 0; t4_ < 16; t4_++) {
        const int tau = t4_ << 2;
        float4 wv[4];
        ulonglong2 bq[4][2];
#pragma unroll
        for (int k = 0; k < 4; k++) {
            wv[k] = *(const float4*)&s_wdtx[(tau + k) * 68 + p0];
            bq[k][0] = *(const ulonglong2*)&s_B[(tau + k) * 132 + n0];
            bq[k][1] = *(const ulonglong2*)&s_B[(tau + k) * 132 + n0 + 4];
        }
#pragma unroll
        for (int k = 0; k < 4; k++) {
            const float* wp = (const float*)&wv[k];
#pragma unroll
            for (int i = 0; i < 4; i++) {
                const uint64_t s = pk2(wp[i]);
                fma2(accp[i][0], s, bq[k][0].x);
                fma2(accp[i][1], s, bq[k][0].y);
                fma2(accp[i][2], s, bq[k][1].x);
                fma2(accp[i][3], s, bq[k][1].y);
            }
        }
    }
    float* dh = g_dH + (size_t)bx * (HD * DSTATE);
#pragma unroll
    for (int i = 0; i < 4; i++) {
        ulonglong2 s0; s0.x = accp[i][0]; s0.y = accp[i][1];
        ulonglong2 s1; s1.x = accp[i][2]; s1.y = accp[i][3];
        *(ulonglong2*)&dh[(p0 + i) * DSTATE + n0]     = s0;
        *(ulonglong2*)&dh[(p0 + i) * DSTATE + n0 + 4] = s1;
    }
}

// ---------------- Phase B: chunk-level recurrence (parallel over state) ----------------
__global__ __launch_bounds__(256) void ssd_phaseB_kernel()
{
    const int gid = blockIdx.x * 256 + threadIdx.x;
    const int bh  = gid >> 11;
    const int e   = (gid & 2047) << 2;

    float4 h = make_float4(0.f, 0.f, 0.f, 0.f);
    const size_t sbase = (size_t)bh * NCHUNK;
    for (int c = 0; c < NCHUNK; c++) {
        const size_t slot = sbase + c;
        const float4 d4 = *(const float4*)&g_dH[slot * (HD * DSTATE) + e];
        *(float4*)&g_hpre[slot * (HD * DSTATE) + e] = h;
        const float P = expf(g_clend[slot]);
        h.x = fmaf(h.x, P, d4.x);
        h.y = fmaf(h.y, P, d4.y);
        h.z = fmaf(h.z, P, d4.z);
        h.w = fmaf(h.w, P, d4.w);
    }
}

// ---------------- Phase C: per-chunk output (fp32 FFMA2; smem overlay, 2 CTA/SM) ----------------
// smem: s_C [64][132] | s_X [128][68] (B^T, then Gm) | s_H [128][68] (h^T) | s_cl[64]
// Pass1 reads C,X,H -> G(regs)+Y2(regs). Sync. Gm overwrites s_X; dtx overwrites s_C. Sync. Pass2.
#define SMC2 ((64*132 + 128*68 + 128*68 + 64) * 4)   // 103,680 B

__global__ __launch_bounds__(256, 2) void ssd_phaseC_kernel(const float* __restrict__ Dp)
{
    extern __shared__ float sm[];
    float* s_C   = sm;                       // [64][132]
    float* s_X   = sm + 64 * 132;            // [128][68]  B^T; later Gm [64][68]
    float* s_H   = s_X + 128 * 68;           // [128][68]  h^T
    float* s_cl  = s_H + 128 * 68;           // [64]
    float* s_Gm  = s_X;                      // alias (pass2)
    float* s_dtx = s_C;                      // alias (pass2), stride 68

    const int tid = threadIdx.x;
    const int bx  = blockIdx.x;
    const int c   = bx & (NCHUNK - 1);
    const int bh  = bx >> 6;
    const int b   = bh >> 5;
    const int h   = bh & 31;
    const int t0row = b * LL + c * CT;
    const float Dh = Dp[h];

#pragma unroll
    for (int i = 0; i < 8; i++) {
        const int f = tid + (i << 8);
        const int row = f >> 5;
        const int q = (f & 31) << 2;
        float4 cv = *(const float4*)&g_xbc[(size_t)(t0row + row) * CONVDIM + DSSM + DSTATE + q];
        *(float4*)&s_C[row * 132 + q] = cv;
        float4 bv = *(const float4*)&g_xbc[(size_t)(t0row + row) * CONVDIM + DSSM + q];
        s_X[(q + 0) * 68 + row] = bv.x;
        s_X[(q + 1) * 68 + row] = bv.y;
        s_X[(q + 2) * 68 + row] = bv.z;
        s_X[(q + 3) * 68 + row] = bv.w;
        const int p = f >> 5;
        float4 hv = *(const float4*)&g_hpre[(size_t)bx * (HD * DSTATE) + p * DSTATE + q];
        s_H[(q + 0) * 68 + p] = hv.x;
        s_H[(q + 1) * 68 + p] = hv.y;
        s_H[(q + 2) * 68 + p] = hv.z;
        s_H[(q + 3) * 68 + p] = hv.w;
    }
    if (tid < CT) s_cl[tid] = g_cumlog[(size_t)bx * CT + tid];
    __syncthreads();

    const int tt = tid >> 4;
    const int tu = tid & 15;
    const int t0 = tt << 2;
    const int u0 = tu << 2;     // same base for G's u-cols and Y2's p-cols

    uint64_t y2[4][2];
    uint64_t gp[4][2];
#pragma unroll
    for (int i = 0; i < 4; i++) {
        y2[i][0] = 0ull; y2[i][1] = 0ull;
        gp[i][0] = 0ull; gp[i][1] = 0ull;
    }

    // ---- fused pass1: G = C @ B^T  AND  Y2 = C @ h^T (shared cv loads) ----
#pragma unroll 2
    for (int n4 = 0; n4 < 32; n4++) {
        const int n = n4 << 2;
        float4 cv[4];
        ulonglong2 bq[4], hq[4];
#pragma unroll
        for (int i = 0; i < 4; i++) cv[i] = *(const float4*)&s_C[(t0 + i) * 132 + n];
#pragma unroll
        for (int k = 0; k < 4; k++) {
            bq[k] = *(const ulonglong2*)&s_X[(n + k) * 68 + u0];
            hq[k] = *(const ulonglong2*)&s_H[(n + k) * 68 + u0];
        }
#pragma unroll
        for (int k = 0; k < 4; k++) {
#pragma unroll
            for (int i = 0; i < 4; i++) {
                const uint64_t s = pk2(((const float*)&cv[i])[k]);
                fma2(gp[i][0], s, bq[k].x);
                fma2(gp[i][1], s, bq[k].y);
                fma2(y2[i][0], s, hq[k].x);
                fma2(y2[i][1], s, hq[k].y);
            }
        }
    }
    __syncthreads();   // everyone done READING s_C / s_X before overwrite

    // mask + decay -> Gm (overwrites s_X region)
#pragma unroll
    for (int i = 0; i < 4; i++) {
        const int t = t0 + i;
        const float clt = s_cl[t];
        const float2 a01 = up2(gp[i][0]);
        const float2 a23 = up2(gp[i][1]);
        const float av[4] = {a01.x, a01.y, a23.x, a23.y};
#pragma unroll
        for (int j = 0; j < 4; j++) {
            const int u = u0 + j;
            s_Gm[t * 68 + u] = (u <= t) ? expf(clt - s_cl[u]) * av[j] : 0.f;
        }
    }
    // stage dtx (overwrites s_C region, stride 68)
#pragma unroll
    for (int i = 0; i < 16; i++) {
        const int f = tid + (i << 8);
        const int tau = f & 63;
        const int p = f >> 6;
        const float dt = g_dtT[(size_t)h * ROWS + t0row + tau];
        const float xv = g_xbc[(size_t)(t0row + tau) * CONVDIM + h * HD + p];
        s_dtx[tau * 68 + p] = dt * xv;
    }
    __syncthreads();

    // ---- pass2: Y1 = Gm @ dtx; combine with Y2, D*x epilogue ----
    {
        const int p0 = tu << 2;
        uint64_t y1[4][2];
#pragma unroll
        for (int i = 0; i < 4; i++) { y1[i][0] = 0ull; y1[i][1] = 0ull; }

#pragma unroll 4
        for (int u4 = 0; u4 < 16; u4++) {
            const int u = u4 << 2;
            float4 gv[4];
            ulonglong2 dq[4];
#pragma unroll
            for (int i = 0; i < 4; i++) gv[i] = *(const float4*)&s_Gm[(t0 + i) * 68 + u];
#pragma unroll
            for (int k = 0; k < 4; k++) dq[k] = *(const ulonglong2*)&s_dtx[(u + k) * 68 + p0];
#pragma unroll
            for (int k = 0; k < 4; k++) {
#pragma unroll
                for (int i = 0; i < 4; i++) {
                    const uint64_t s = pk2(((const float*)&gv[i])[k]);
                    fma2(y1[i][0], s, dq[k].x);
                    fma2(y1[i][1], s, dq[k].y);
                }
            }
        }
#pragma unroll
        for (int i = 0; i < 4; i++) {
            const int t = t0 + i;
            const int row = t0row + t;
            const float et = expf(s_cl[t]);
            const float2 a01 = up2(y1[i][0]);
            const float2 a23 = up2(y1[i][1]);
            const float2 b01 = up2(y2[i][0]);
            const float2 b23 = up2(y2[i][1]);
            float4 xv = *(const float4*)&g_xbc[(size_t)row * CONVDIM + h * HD + p0];
            float4 y4;
            y4.x = fmaf(et, b01.x, a01.x) + Dh * xv.x;
            y4.y = fmaf(et, b01.y, a01.y) + Dh * xv.y;
            y4.z = fmaf(et, b23.x, a23.x) + Dh * xv.z;
            y4.w = fmaf(et, b23.y, a23.y) + Dh * xv.w;
            *(float4*)&g_y[(size_t)row * DSSM + h * HD + p0] = y4;
        }
    }
}

// ---------------- gate (silu(z)) + RMSNorm -> fp16 output for GEMM2 ----------------
__global__ __launch_bounds__(256) void gate_rmsnorm_kernel(const float* __restrict__ norm_w)
{
    const int row = blockIdx.x;
    const int tid = threadIdx.x;
    const int w = tid >> 5, lane = tid & 31;

    float vals[8];
    float ss = 0.f;
#pragma unroll
    for (int i = 0; i < 8; i++) {
        int e = i * 256 + tid;
        float z = g_zxbcdt[(size_t)row * DPROJ + e];
        float yv = g_y[(size_t)row * DSSM + e];
        float g = yv * silu_f(z);
        vals[i] = g;
        ss = fmaf(g, g, ss);
    }
    ss += __shfl_xor_sync(0xffffffffu, ss, 16);
    ss += __shfl_xor_sync(0xffffffffu, ss, 8);
    ss += __shfl_xor_sync(0xffffffffu, ss, 4);
    ss += __shfl_xor_sync(0xffffffffu, ss, 2);
    ss += __shfl_xor_sync(0xffffffffu, ss, 1);

    __shared__ float red[8];
    __shared__ float sscale;
    if (lane == 0) red[w] = ss;
    __syncthreads();
    if (tid == 0) {
        float s = 0.f;
#pragma unroll
        for (int k = 0; k < 8; k++) s += red[k];
        sscale = rsqrtf(s / (float)DSSM + EPSV);
    }
    __syncthreads();
    const float scale = sscale;
#pragma unroll
    for (int i = 0; i < 8; i++) {
        int e = i * 256 + tid;
        g_gh[(size_t)row * DSSM + e] = __float2half(vals[i] * scale * norm_w[e]);
    }
}

// ---------------- entry ----------------
extern "C" void kernel_launch(void* const* d_in, const int* in_sizes, int n_in,
                              void* d_out, int out_size)
{
    const float* u       = (const float*)d_in[0];
    const float* W_in    = (const float*)d_in[1];
    const float* conv_w  = (const float*)d_in[2];
    const float* conv_b  = (const float*)d_in[3];
    const float* dt_bias = (const float*)d_in[4];
    const float* A_log   = (const float*)d_in[5];
    const float* Dp      = (const float*)d_in[6];
    const float* norm_w  = (const float*)d_in[7];
    const float* W_out   = (const float*)d_in[8];
    float* out = (float*)d_out;

    float*  zx;  cudaGetSymbolAddress((void**)&zx,  g_zxbcdt);
    __half* uh;  cudaGetSymbolAddress((void**)&uh,  g_uh);
    __half* wih; cudaGetSymbolAddress((void**)&wih, g_Winh);
    __half* gh;  cudaGetSymbolAddress((void**)&gh,  g_gh);
    __half* woh; cudaGetSymbolAddress((void**)&woh, g_Wouth);

    const int smA = (64 * 132 + 64 * 68 + 64 + 64) * 4;
    cudaFuncSetAttribute(ssd_phaseA_kernel, cudaFuncAttributeMaxDynamicSharedMemorySize, smA);
    cudaFuncSetAttribute(ssd_phaseC_kernel, cudaFuncAttributeMaxDynamicSharedMemorySize, SMC2);

    // 0) fp16 conversions
    {
        size_t nu = (size_t)ROWS * DMODEL;
        f2h_kernel<<<(unsigned)((nu / 4 + 255) / 256), 256>>>(u, uh, nu);
        size_t nw = (size_t)DPROJ * DMODEL;
        f2h_kernel<<<(unsigned)((nw / 4 + 255) / 256), 256>>>(W_in, wih, nw);
        size_t no = (size_t)DMODEL * DSSM;
        f2h_kernel<<<(unsigned)((no / 4 + 255) / 256), 256>>>(W_out, woh, no);
    }
    // 1) in-projection
    {
        dim3 grid((DPROJ + 127) / 128, ROWS / 128);
        hgemm_nt_kernel<<<grid, 256>>>(uh, wih, zx, ROWS, DPROJ, DMODEL);
    }
    // 2) conv + silu (4 t's per thread)
    {
        int total = BB * (LL / 4) * CONVDIM;
        conv_silu_kernel<<<(total + 255) / 256, 256>>>(conv_w, conv_b);
    }
    // 3) dt softplus + log decay
    dt_kernel<<<(ROWS * NH + 255) / 256, 256>>>(dt_bias, A_log);
    // 4) chunked SSD scan
    ssd_phaseA_kernel<<<NSLOT, 256, smA>>>();
    ssd_phaseB_kernel<<<512, 256>>>();
    ssd_phaseC_kernel<<<NSLOT, 256, SMC2>>>(Dp);
    // 5) gate + rmsnorm
    gate_rmsnorm_kernel<<<ROWS, 256>>>(norm_w);
    // 6) out-projection
    {
        dim3 grid(DMODEL / 128, ROWS / 128);
        hgemm_nt_kernel<<<grid, 256>>>(gh, woh, out, ROWS, DMODEL, DSSM);
    }
}

// round 15
// speedup vs baseline: 1.2107x; 1.0213x over previous
#include <cuda_runtime.h>
#include <cuda_fp16.h>
#include <math.h>
#include <stdint.h>

// ---------------- Problem constants ----------------
#define BB      2
#define LL      4096
#define DMODEL  1024
#define DSSM    2048
#define DSTATE  128
#define DCONV   4
#define NH      32
#define HD      64
#define CONVDIM (DSSM + 2*DSTATE)          // 2304
#define DPROJ   (2*DSSM + 2*DSTATE + NH)   // 4384
#define EPSV    1e-5f

#define ROWS    (BB*LL)                    // 8192
#define CT      64                         // chunk length
#define NCHUNK  (LL/CT)                    // 64
#define NSLOT   (BB*NH*NCHUNK)             // 4096

// ---------------- Scratch (static device arrays; no allocation) ----------------
__device__ float  g_zxbcdt[(size_t)ROWS * DPROJ];
__device__ float  g_xbc[(size_t)ROWS * CONVDIM];
__device__ float  g_dtT[(size_t)NH * ROWS];
__device__ float  g_ldAT[(size_t)NH * ROWS];
__device__ float  g_y[(size_t)ROWS * DSSM];
__device__ __half g_dHh[(size_t)NSLOT * HD * DSTATE];    // chunk state increments (fp16)
__device__ __half g_hpreh[(size_t)NSLOT * HD * DSTATE];  // chunk state prefixes (fp16)
__device__ float  g_cumlog[(size_t)NSLOT * CT];
__device__ float  g_clend[NSLOT];
__device__ __half g_uh[(size_t)ROWS * DMODEL];
__device__ __half g_Winh[(size_t)DPROJ * DMODEL];
__device__ __half g_gh[(size_t)ROWS * DSSM];
__device__ __half g_Wouth[(size_t)DMODEL * DSSM];

// ---------------- helpers ----------------
__device__ __forceinline__ float silu_f(float x) {
    return x / (1.0f + expf(-x));
}

__device__ __forceinline__ uint32_t smem_u32(const void* p) {
    uint32_t a;
    asm("{ .reg .u64 t; cvta.to.shared.u64 t, %1; cvt.u32.u64 %0, t; }" : "=r"(a) : "l"(p));
    return a;
}

__device__ __forceinline__ void ldsm4(uint32_t &r0, uint32_t &r1, uint32_t &r2, uint32_t &r3,
                                      uint32_t saddr) {
    asm volatile("ldmatrix.sync.aligned.m8n8.x4.shared.b16 {%0,%1,%2,%3}, [%4];"
                 : "=r"(r0), "=r"(r1), "=r"(r2), "=r"(r3)
                 : "r"(saddr));
}

__device__ __forceinline__ void cp_async16(uint32_t dst, const void* src, int srcsize) {
    asm volatile("cp.async.cg.shared.global [%0], [%1], 16, %2;"
                 :: "r"(dst), "l"(src), "r"(srcsize) : "memory");
}

__device__ __forceinline__ void mma16816(float* d, const uint32_t* a, const uint32_t* b) {
    asm volatile(
        "mma.sync.aligned.m16n8k16.row.col.f32.f16.f16.f32 "
        "{%0,%1,%2,%3}, {%4,%5,%6,%7}, {%8,%9}, {%0,%1,%2,%3};"
        : "+f"(d[0]), "+f"(d[1]), "+f"(d[2]), "+f"(d[3])
        : "r"(a[0]), "r"(a[1]), "r"(a[2]), "r"(a[3]), "r"(b[0]), "r"(b[1]));
}

// ---- packed fp32x2 (FFMA2) helpers ----
__device__ __forceinline__ uint64_t pk2(float x) {
    uint64_t r;
    asm("mov.b64 %0, {%1, %1};" : "=l"(r) : "f"(x));
    return r;
}
__device__ __forceinline__ void fma2(uint64_t &d, uint64_t a, uint64_t b) {
    asm("fma.rn.f32x2 %0, %1, %2, %0;" : "+l"(d) : "l"(a), "l"(b));
}
__device__ __forceinline__ float2 up2(uint64_t v) {
    float2 r;
    asm("mov.b64 {%0, %1}, %2;" : "=f"(r.x), "=f"(r.y) : "l"(v));
    return r;
}

// ---------------- fp16 tensor-core GEMM, 3-stage cp.async pipeline (NT) ----------------
__global__ __launch_bounds__(256, 2) void hgemm_nt_kernel(
    const __half* __restrict__ A, const __half* __restrict__ B, float* __restrict__ C,
    int M, int N, int K)
{
    __shared__ __align__(16) __half As[3][128][40];
    __shared__ __align__(16) __half Bs[3][128][40];

    const int tid  = threadIdx.x;
    const int warp = tid >> 5;
    const int lane = tid & 31;
    const int g    = lane >> 2;
    const int t4   = lane & 3;
    const int wm   = (warp >> 1) * 32;
    const int wn   = (warp & 1) * 64;
    const int m0   = blockIdx.y * 128;
    const int n0   = blockIdx.x * 128;

    const int lm  = lane >> 3;
    const int lr  = lane & 7;
    const int arow = (lm & 1) * 8 + lr;
    const int acol = (lm >> 1) * 8;
    const int brow = (lm >> 1) * 8 + lr;
    const int bcol = (lm & 1) * 8;

    const uint32_t as_b = smem_u32(&As[0][0][0]);
    const uint32_t bs_b = smem_u32(&Bs[0][0][0]);
    const uint32_t BUFB = 128u * 40u * 2u;

    float d[2][8][4];
#pragma unroll
    for (int i = 0; i < 2; i++)
#pragma unroll
        for (int j = 0; j < 8; j++)
#pragma unroll
            for (int v = 0; v < 4; v++) d[i][j][v] = 0.0f;

    const int nch = K >> 5;

    auto stage = [&](int kc, int buf) {
        const int kb = kc << 5;
#pragma unroll
        for (int i = 0; i < 2; i++) {
            const int f   = tid + (i << 8);
            const int row = f >> 2;
            const int seg = f & 3;
            const uint32_t off = (uint32_t)(row * 80 + seg * 16);
            cp_async16(as_b + (uint32_t)buf * BUFB + off,
                       &A[(size_t)(m0 + row) * K + kb + seg * 8], 16);
            const int nr = n0 + row;
            const int ok = (nr < N);
            cp_async16(bs_b + (uint32_t)buf * BUFB + off,
                       &B[(size_t)(ok ? nr : 0) * K + kb + seg * 8], ok ? 16 : 0);
        }
        asm volatile("cp.async.commit_group;" ::: "memory");
    };

    stage(0, 0);
    if (nch > 1) stage(1, 1);

    for (int kc = 0; kc < nch; kc++) {
        const int buf = kc % 3;
        if (kc + 1 < nch) {
            asm volatile("cp.async.wait_group 1;" ::: "memory");
        } else {
            asm volatile("cp.async.wait_group 0;" ::: "memory");
        }
        __syncthreads();
        if (kc + 2 < nch) stage(kc + 2, (kc + 2) % 3);

        const uint32_t ab = as_b + (uint32_t)buf * BUFB;
        const uint32_t bb = bs_b + (uint32_t)buf * BUFB;
#pragma unroll
        for (int s = 0; s < 2; s++) {
            const int kk = s * 16;
            uint32_t af[2][4];
#pragma unroll
            for (int mt = 0; mt < 2; mt++) {
                uint32_t addr = ab + (uint32_t)(((wm + mt * 16 + arow) * 40 + kk + acol) * 2);
                ldsm4(af[mt][0], af[mt][1], af[mt][2], af[mt][3], addr);
            }
            uint32_t bf[8][2];
#pragma unroll
            for (int ntp = 0; ntp < 4; ntp++) {
                uint32_t q0, q1, q2, q3;
                uint32_t addr = bb + (uint32_t)(((wn + ntp * 16 + brow) * 40 + kk + bcol) * 2);
                ldsm4(q0, q1, q2, q3, addr);
                bf[2 * ntp][0]     = q0;  bf[2 * ntp][1]     = q1;
                bf[2 * ntp + 1][0] = q2;  bf[2 * ntp + 1][1] = q3;
            }
#pragma unroll
            for (int mt = 0; mt < 2; mt++) {
#pragma unroll
                for (int nt = 0; nt < 8; nt++) {
                    mma16816(d[mt][nt], af[mt], bf[nt]);
                }
            }
        }
    }

#pragma unroll
    for (int mt = 0; mt < 2; mt++) {
        const int mrow = m0 + wm + mt * 16;
#pragma unroll
        for (int nt = 0; nt < 8; nt++) {
            const int ncol = n0 + wn + nt * 8 + t4 * 2;
            if (ncol < N) {
                *(float2*)&C[(size_t)(mrow + g    ) * N + ncol] =
                    make_float2(d[mt][nt][0], d[mt][nt][1]);
                *(float2*)&C[(size_t)(mrow + g + 8) * N + ncol] =
                    make_float2(d[mt][nt][2], d[mt][nt][3]);
            }
        }
    }
}

// ---------------- fp32 -> fp16 conversion (vectorized) ----------------
__global__ __launch_bounds__(256) void f2h_kernel(const float* __restrict__ src,
                                                  __half* __restrict__ dst, size_t n)
{
    size_t i = ((size_t)blockIdx.x * blockDim.x + threadIdx.x) * 4;
    if (i >= n) return;
    float4 v = *(const float4*)&src[i];
    __half2* d2 = (__half2*)&dst[i];
    d2[0] = __floats2half2_rn(v.x, v.y);
    d2[1] = __floats2half2_rn(v.z, v.w);
}

// ---------------- conv1d (width 4, causal) + bias + SiLU: 4 t's per thread ----------------
__global__ __launch_bounds__(256) void conv_silu_kernel(
    const float* __restrict__ conv_w, const float* __restrict__ conv_b)
{
    const int TB = LL / 4;                                  // 1024 t-blocks per batch
    int idx = blockIdx.x * 256 + threadIdx.x;
    if (idx >= BB * TB * CONVDIM) return;
    const int c  = idx % CONVDIM;
    const int tb = idx / CONVDIM;
    const int t0 = (tb % TB) * 4;
    const int b  = tb / TB;

    const float w0 = conv_w[c * DCONV + 0];
    const float w1 = conv_w[c * DCONV + 1];
    const float w2 = conv_w[c * DCONV + 2];
    const float w3 = conv_w[c * DCONV + 3];
    const float bias = conv_b[c];

    const size_t base = (size_t)(b * LL) * DPROJ + DSSM + c;
    float x[7];
#pragma unroll
    for (int j = 0; j < 7; j++) {
        const int ts = t0 - 3 + j;
        x[j] = (ts >= 0) ? g_zxbcdt[base + (size_t)ts * DPROJ] : 0.0f;
    }
#pragma unroll
    for (int k = 0; k < 4; k++) {
        float acc = bias;
        acc = fmaf(x[k + 0], w0, acc);
        acc = fmaf(x[k + 1], w1, acc);
        acc = fmaf(x[k + 2], w2, acc);
        acc = fmaf(x[k + 3], w3, acc);
        g_xbc[(size_t)(b * LL + t0 + k) * CONVDIM + c] = silu_f(acc);
    }
}

// ---------------- dt softplus + log-decay (transposed layouts) ----------------
__global__ __launch_bounds__(256) void dt_kernel(
    const float* __restrict__ dt_bias, const float* __restrict__ A_log)
{
    int idx = blockIdx.x * blockDim.x + threadIdx.x;
    if (idx >= ROWS * NH) return;
    int h = idx % NH;
    int r = idx / NH;
    float raw = g_zxbcdt[(size_t)r * DPROJ + DSSM + CONVDIM + h] + dt_bias[h];
    float dt = (raw > 20.0f) ? raw : log1pf(expf(raw));
    float Aneg = -expf(A_log[h]);
    g_dtT[(size_t)h * ROWS + r] = dt;
    g_ldAT[(size_t)h * ROWS + r] = dt * Aneg;
}

// ================= Chunked SSD scan =================

// ---------------- Phase A: per-chunk state increment (fp32 FFMA2; fp16 dH store) ----------------
__global__ __launch_bounds__(256) void ssd_phaseA_kernel()
{
    extern __shared__ float sm[];
    float* s_B    = sm;                    // [64][132]
    float* s_wdtx = sm + 64 * 132;         // [64][68]
    float* s_w    = s_wdtx + 64 * 68;      // [64]
    float* s_cl   = s_w + 64;              // [64]

    const int tid = threadIdx.x;
    const int bx  = blockIdx.x;
    const int c   = bx & (NCHUNK - 1);
    const int bh  = bx >> 6;
    const int b   = bh >> 5;
    const int h   = bh & 31;
    const int t0row = b * LL + c * CT;

    if (tid == 0) {
        float cl = 0.f;
        const float* ld = g_ldAT + (size_t)h * ROWS + t0row;
#pragma unroll 4
        for (int t = 0; t < CT; t++) { cl += ld[t]; s_cl[t] = cl; }
    }
#pragma unroll
    for (int i = 0; i < 8; i++) {
        const int f = tid + (i << 8);
        const int row = f >> 5;
        const int q = (f & 31) << 2;
        float4 v = *(const float4*)&g_xbc[(size_t)(t0row + row) * CONVDIM + DSSM + q];
        *(float4*)&s_B[row * 132 + q] = v;
    }
    __syncthreads();

    const float cend = s_cl[CT - 1];
    if (tid < CT) {
        s_w[tid] = expf(cend - s_cl[tid]);
        g_cumlog[(size_t)bx * CT + tid] = s_cl[tid];
        if (tid == 0) g_clend[bx] = cend;
    }
    __syncthreads();

#pragma unroll
    for (int i = 0; i < 16; i++) {
        const int f = tid + (i << 8);
        const int tau = f & 63;
        const int p = f >> 6;
        const float dt = g_dtT[(size_t)h * ROWS + t0row + tau];
        const float xv = g_xbc[(size_t)(t0row + tau) * CONVDIM + h * HD + p];
        s_wdtx[tau * 68 + p] = s_w[tau] * dt * xv;
    }
    __syncthreads();

    const int pp = tid >> 4;
    const int nu = tid & 15;
    const int p0 = pp << 2;
    const int n0 = nu << 3;
    uint64_t accp[4][4];
#pragma unroll
    for (int i = 0; i < 4; i++)
#pragma unroll
        for (int j = 0; j < 4; j++) accp[i][j] = 0ull;

#pragma unroll 4
    for (int t4_ = 0; t4_ < 16; t4_++) {
        const int tau = t4_ << 2;
        float4 wv[4];
        ulonglong2 bq[4][2];
#pragma unroll
        for (int k = 0; k < 4; k++) {
            wv[k] = *(const float4*)&s_wdtx[(tau + k) * 68 + p0];
            bq[k][0] = *(const ulonglong2*)&s_B[(tau + k) * 132 + n0];
            bq[k][1] = *(const ulonglong2*)&s_B[(tau + k) * 132 + n0 + 4];
        }
#pragma unroll
        for (int k = 0; k < 4; k++) {
            const float* wp = (const float*)&wv[k];
#pragma unroll
            for (int i = 0; i < 4; i++) {
                const uint64_t s = pk2(wp[i]);
                fma2(accp[i][0], s, bq[k][0].x);
                fma2(accp[i][1], s, bq[k][0].y);
                fma2(accp[i][2], s, bq[k][1].x);
                fma2(accp[i][3], s, bq[k][1].y);
            }
        }
    }
    // store dH as fp16 (8 halfs = 16B per row-segment)
    __half* dh = g_dHh + (size_t)bx * (HD * DSTATE);
#pragma unroll
    for (int i = 0; i < 4; i++) {
        const float2 v0 = up2(accp[i][0]);
        const float2 v1 = up2(accp[i][1]);
        const float2 v2 = up2(accp[i][2]);
        const float2 v3 = up2(accp[i][3]);
        __half2 hh[4];
        hh[0] = __floats2half2_rn(v0.x, v0.y);
        hh[1] = __floats2half2_rn(v1.x, v1.y);
        hh[2] = __floats2half2_rn(v2.x, v2.y);
        hh[3] = __floats2half2_rn(v3.x, v3.y);
        *(ulonglong2*)&dh[(p0 + i) * DSTATE + n0] = *(ulonglong2*)hh;
    }
}

// ---------------- Phase B: chunk-level recurrence (fp32 carry; fp16 streams) ----------------
__global__ __launch_bounds__(256) void ssd_phaseB_kernel()
{
    const int gid = blockIdx.x * 256 + threadIdx.x;
    const int bh  = gid >> 11;
    const int e   = (gid & 2047) << 2;

    float4 h = make_float4(0.f, 0.f, 0.f, 0.f);
    const size_t sbase = (size_t)bh * NCHUNK;
    for (int c = 0; c < NCHUNK; c++) {
        const size_t slot = sbase + c;
        const __half2* dsrc = (const __half2*)&g_dHh[slot * (HD * DSTATE) + e];
        const __half2 dh0 = dsrc[0], dh1 = dsrc[1];
        // write prefix (state BEFORE chunk c) as fp16
        __half2* hp = (__half2*)&g_hpreh[slot * (HD * DSTATE) + e];
        hp[0] = __floats2half2_rn(h.x, h.y);
        hp[1] = __floats2half2_rn(h.z, h.w);
        const float2 d01 = __half22float2(dh0);
        const float2 d23 = __half22float2(dh1);
        const float P = expf(g_clend[slot]);
        h.x = fmaf(h.x, P, d01.x);
        h.y = fmaf(h.y, P, d01.y);
        h.z = fmaf(h.z, P, d23.x);
        h.w = fmaf(h.w, P, d23.y);
    }
}

// ---------------- Phase C: per-chunk output (fp32 FFMA2; smem overlay, 2 CTA/SM) ----------------
#define SMC2 ((64*132 + 128*68 + 128*68 + 64) * 4)   // 103,680 B

__global__ __launch_bounds__(256, 2) void ssd_phaseC_kernel(const float* __restrict__ Dp)
{
    extern __shared__ float sm[];
    float* s_C   = sm;                       // [64][132]
    float* s_X   = sm + 64 * 132;            // [128][68]  B^T; later Gm [64][68]
    float* s_H   = s_X + 128 * 68;           // [128][68]  h^T (fp32 in smem)
    float* s_cl  = s_H + 128 * 68;           // [64]
    float* s_Gm  = s_X;                      // alias (pass2)
    float* s_dtx = s_C;                      // alias (pass2), stride 68

    const int tid = threadIdx.x;
    const int bx  = blockIdx.x;
    const int c   = bx & (NCHUNK - 1);
    const int bh  = bx >> 6;
    const int b   = bh >> 5;
    const int h   = bh & 31;
    const int t0row = b * LL + c * CT;
    const float Dh = Dp[h];

#pragma unroll
    for (int i = 0; i < 8; i++) {
        const int f = tid + (i << 8);
        const int row = f >> 5;
        const int q = (f & 31) << 2;
        float4 cv = *(const float4*)&g_xbc[(size_t)(t0row + row) * CONVDIM + DSSM + DSTATE + q];
        *(float4*)&s_C[row * 132 + q] = cv;
        float4 bv = *(const float4*)&g_xbc[(size_t)(t0row + row) * CONVDIM + DSSM + q];
        s_X[(q + 0) * 68 + row] = bv.x;
        s_X[(q + 1) * 68 + row] = bv.y;
        s_X[(q + 2) * 68 + row] = bv.z;
        s_X[(q + 3) * 68 + row] = bv.w;
        const int p = f >> 5;
        const __half2* hsrc = (const __half2*)&g_hpreh[(size_t)bx * (HD * DSTATE) + p * DSTATE + q];
        const float2 h01 = __half22float2(hsrc[0]);
        const float2 h23 = __half22float2(hsrc[1]);
        s_H[(q + 0) * 68 + p] = h01.x;
        s_H[(q + 1) * 68 + p] = h01.y;
        s_H[(q + 2) * 68 + p] = h23.x;
        s_H[(q + 3) * 68 + p] = h23.y;
    }
    if (tid < CT) s_cl[tid] = g_cumlog[(size_t)bx * CT + tid];
    __syncthreads();

    const int tt = tid >> 4;
    const int tu = tid & 15;
    const int t0 = tt << 2;
    const int u0 = tu << 2;     // same base for G's u-cols and Y2's p-cols

    uint64_t y2[4][2];
    uint64_t gp[4][2];
#pragma unroll
    for (int i = 0; i < 4; i++) {
        y2[i][0] = 0ull; y2[i][1] = 0ull;
        gp[i][0] = 0ull; gp[i][1] = 0ull;
    }

    // ---- fused pass1: G = C @ B^T  AND  Y2 = C @ h^T (shared cv loads) ----
#pragma unroll 2
    for (int n4 = 0; n4 < 32; n4++) {
        const int n = n4 << 2;
        float4 cv[4];
        ulonglong2 bq[4], hq[4];
#pragma unroll
        for (int i = 0; i < 4; i++) cv[i] = *(const float4*)&s_C[(t0 + i) * 132 + n];
#pragma unroll
        for (int k = 0; k < 4; k++) {
            bq[k] = *(const ulonglong2*)&s_X[(n + k) * 68 + u0];
            hq[k] = *(const ulonglong2*)&s_H[(n + k) * 68 + u0];
        }
#pragma unroll
        for (int k = 0; k < 4; k++) {
#pragma unroll
            for (int i = 0; i < 4; i++) {
                const uint64_t s = pk2(((const float*)&cv[i])[k]);
                fma2(gp[i][0], s, bq[k].x);
                fma2(gp[i][1], s, bq[k].y);
                fma2(y2[i][0], s, hq[k].x);
                fma2(y2[i][1], s, hq[k].y);
            }
        }
    }
    __syncthreads();   // everyone done READING s_C / s_X before overwrite

    // mask + decay -> Gm (overwrites s_X region)
#pragma unroll
    for (int i = 0; i < 4; i++) {
        const int t = t0 + i;
        const float clt = s_cl[t];
        const float2 a01 = up2(gp[i][0]);
        const float2 a23 = up2(gp[i][1]);
        const float av[4] = {a01.x, a01.y, a23.x, a23.y};
#pragma unroll
        for (int j = 0; j < 4; j++) {
            const int u = u0 + j;
            s_Gm[t * 68 + u] = (u <= t) ? expf(clt - s_cl[u]) * av[j] : 0.f;
        }
    }
    // stage dtx (overwrites s_C region, stride 68)
#pragma unroll
    for (int i = 0; i < 16; i++) {
        const int f = tid + (i << 8);
        const int tau = f & 63;
        const int p = f >> 6;
        const float dt = g_dtT[(size_t)h * ROWS + t0row + tau];
        const float xv = g_xbc[(size_t)(t0row + tau) * CONVDIM + h * HD + p];
        s_dtx[tau * 68 + p] = dt * xv;
    }
    __syncthreads();

    // ---- pass2: Y1 = Gm @ dtx; combine with Y2, D*x epilogue ----
    {
        const int p0 = tu << 2;
        uint64_t y1[4][2];
#pragma unroll
        for (int i = 0; i < 4; i++) { y1[i][0] = 0ull; y1[i][1] = 0ull; }

#pragma unroll 4
        for (int u4 = 0; u4 < 16; u4++) {
            const int u = u4 << 2;
            float4 gv[4];
            ulonglong2 dq[4];
#pragma unroll
            for (int i = 0; i < 4; i++) gv[i] = *(const float4*)&s_Gm[(t0 + i) * 68 + u];
#pragma unroll
            for (int k = 0; k < 4; k++) dq[k] = *(const ulonglong2*)&s_dtx[(u + k) * 68 + p0];
#pragma unroll
            for (int k = 0; k < 4; k++) {
#pragma unroll
                for (int i = 0; i < 4; i++) {
                    const uint64_t s = pk2(((const float*)&gv[i])[k]);
                    fma2(y1[i][0], s, dq[k].x);
                    fma2(y1[i][1], s, dq[k].y);
                }
            }
        }
#pragma unroll
        for (int i = 0; i < 4; i++) {
            const int t = t0 + i;
            const int row = t0row + t;
            const float et = expf(s_cl[t]);
            const float2 a01 = up2(y1[i][0]);
            const float2 a23 = up2(y1[i][1]);
            const float2 b01 = up2(y2[i][0]);
            const float2 b23 = up2(y2[i][1]);
            float4 xv = *(const float4*)&g_xbc[(size_t)row * CONVDIM + h * HD + p0];
            float4 y4;
            y4.x = fmaf(et, b01.x, a01.x) + Dh * xv.x;
            y4.y = fmaf(et, b01.y, a01.y) + Dh * xv.y;
            y4.z = fmaf(et, b23.x, a23.x) + Dh * xv.z;
            y4.w = fmaf(et, b23.y, a23.y) + Dh * xv.w;
            *(float4*)&g_y[(size_t)row * DSSM + h * HD + p0] = y4;
        }
    }
}

// ---------------- gate (silu(z)) + RMSNorm -> fp16 output for GEMM2 ----------------
__global__ __launch_bounds__(256) void gate_rmsnorm_kernel(const float* __restrict__ norm_w)
{
    const int row = blockIdx.x;
    const int tid = threadIdx.x;
    const int w = tid >> 5, lane = tid & 31;

    float vals[8];
    float ss = 0.f;
#pragma unroll
    for (int i = 0; i < 8; i++) {
        int e = i * 256 + tid;
        float z = g_zxbcdt[(size_t)row * DPROJ + e];
        float yv = g_y[(size_t)row * DSSM + e];
        float g = yv * silu_f(z);
        vals[i] = g;
        ss = fmaf(g, g, ss);
    }
    ss += __shfl_xor_sync(0xffffffffu, ss, 16);
    ss += __shfl_xor_sync(0xffffffffu, ss, 8);
    ss += __shfl_xor_sync(0xffffffffu, ss, 4);
    ss += __shfl_xor_sync(0xffffffffu, ss, 2);
    ss += __shfl_xor_sync(0xffffffffu, ss, 1);

    __shared__ float red[8];
    __shared__ float sscale;
    if (lane == 0) red[w] = ss;
    __syncthreads();
    if (tid == 0) {
        float s = 0.f;
#pragma unroll
        for (int k = 0; k < 8; k++) s += red[k];
        sscale = rsqrtf(s / (float)DSSM + EPSV);
    }
    __syncthreads();
    const float scale = sscale;
#pragma unroll
    for (int i = 0; i < 8; i++) {
        int e = i * 256 + tid;
        g_gh[(size_t)row * DSSM + e] = __float2half(vals[i] * scale * norm_w[e]);
    }
}

// ---------------- entry ----------------
extern "C" void kernel_launch(void* const* d_in, const int* in_sizes, int n_in,
                              void* d_out, int out_size)
{
    const float* u       = (const float*)d_in[0];
    const float* W_in    = (const float*)d_in[1];
    const float* conv_w  = (const float*)d_in[2];
    const float* conv_b  = (const float*)d_in[3];
    const float* dt_bias = (const float*)d_in[4];
    const float* A_log   = (const float*)d_in[5];
    const float* Dp      = (const float*)d_in[6];
    const float* norm_w  = (const float*)d_in[7];
    const float* W_out   = (const float*)d_in[8];
    float* out = (float*)d_out;

    float*  zx;  cudaGetSymbolAddress((void**)&zx,  g_zxbcdt);
    __half* uh;  cudaGetSymbolAddress((void**)&uh,  g_uh);
    __half* wih; cudaGetSymbolAddress((void**)&wih, g_Winh);
    __half* gh;  cudaGetSymbolAddress((void**)&gh,  g_gh);
    __half* woh; cudaGetSymbolAddress((void**)&woh, g_Wouth);

    const int smA = (64 * 132 + 64 * 68 + 64 + 64) * 4;
    cudaFuncSetAttribute(ssd_phaseA_kernel, cudaFuncAttributeMaxDynamicSharedMemorySize, smA);
    cudaFuncSetAttribute(ssd_phaseC_kernel, cudaFuncAttributeMaxDynamicSharedMemorySize, SMC2);

    // 0) fp16 conversions
    {
        size_t nu = (size_t)ROWS * DMODEL;
        f2h_kernel<<<(unsigned)((nu / 4 + 255) / 256), 256>>>(u, uh, nu);
        size_t nw = (size_t)DPROJ * DMODEL;
        f2h_kernel<<<(unsigned)((nw / 4 + 255) / 256), 256>>>(W_in, wih, nw);
        size_t no = (size_t)DMODEL * DSSM;
        f2h_kernel<<<(unsigned)((no / 4 + 255) / 256), 256>>>(W_out, woh, no);
    }
    // 1) in-projection
    {
        dim3 grid((DPROJ + 127) / 128, ROWS / 128);
        hgemm_nt_kernel<<<grid, 256>>>(uh, wih, zx, ROWS, DPROJ, DMODEL);
    }
    // 2) conv + silu (4 t's per thread)
    {
        int total = BB * (LL / 4) * CONVDIM;
        conv_silu_kernel<<<(total + 255) / 256, 256>>>(conv_w, conv_b);
    }
    // 3) dt softplus + log decay
    dt_kernel<<<(ROWS * NH + 255) / 256, 256>>>(dt_bias, A_log);
    // 4) chunked SSD scan
    ssd_phaseA_kernel<<<NSLOT, 256, smA>>>();
    ssd_phaseB_kernel<<<512, 256>>>();
    ssd_phaseC_kernel<<<NSLOT, 256, SMC2>>>(Dp);
    // 5) gate + rmsnorm
    gate_rmsnorm_kernel<<<ROWS, 256>>>(norm_w);
    // 6) out-projection
    {
        dim3 grid(DMODEL / 128, ROWS / 128);
        hgemm_nt_kernel<<<grid, 256>>>(gh, woh, out, ROWS, DMODEL, DSSM);
    }
}

// round 16
// speedup vs baseline: 1.3877x; 1.1462x over previous
#include <cuda_runtime.h>
#include <cuda_fp16.h>
#include <math.h>
#include <stdint.h>

// ---------------- Problem constants ----------------
#define BB      2
#define LL      4096
#define DMODEL  1024
#define DSSM    2048
#define DSTATE  128
#define DCONV   4
#define NH      32
#define HD      64
#define CONVDIM (DSSM + 2*DSTATE)          // 2304
#define DPROJ   (2*DSSM + 2*DSTATE + NH)   // 4384
#define EPSV    1e-5f

#define ROWS    (BB*LL)                    // 8192
#define CT      64                         // chunk length
#define NCHUNK  (LL/CT)                    // 64
#define NSLOT   (BB*NH*NCHUNK)             // 4096

// ---------------- Scratch (static device arrays; no allocation) ----------------
__device__ float  g_zxbcdt[(size_t)ROWS * DPROJ];
__device__ float  g_xbc[(size_t)ROWS * CONVDIM];
__device__ float  g_dtT[(size_t)NH * ROWS];
__device__ float  g_ldAT[(size_t)NH * ROWS];
__device__ float  g_y[(size_t)ROWS * DSSM];
__device__ __half g_dHh[(size_t)NSLOT * HD * DSTATE];    // chunk state increments (fp16)
__device__ __half g_hpreh[(size_t)NSLOT * HD * DSTATE];  // chunk state prefixes (fp16)
__device__ float  g_cumlog[(size_t)NSLOT * CT];
__device__ float  g_clend[NSLOT];
__device__ __half g_uh[(size_t)ROWS * DMODEL];
__device__ __half g_Winh[(size_t)DPROJ * DMODEL];
__device__ __half g_gh[(size_t)ROWS * DSSM];
__device__ __half g_Wouth[(size_t)DMODEL * DSSM];

// ---------------- helpers ----------------
__device__ __forceinline__ float silu_f(float x) {
    return x / (1.0f + expf(-x));
}

__device__ __forceinline__ uint32_t smem_u32(const void* p) {
    uint32_t a;
    asm("{ .reg .u64 t; cvta.to.shared.u64 t, %1; cvt.u32.u64 %0, t; }" : "=r"(a) : "l"(p));
    return a;
}

__device__ __forceinline__ void ldsm4(uint32_t &r0, uint32_t &r1, uint32_t &r2, uint32_t &r3,
                                      uint32_t saddr) {
    asm volatile("ldmatrix.sync.aligned.m8n8.x4.shared.b16 {%0,%1,%2,%3}, [%4];"
                 : "=r"(r0), "=r"(r1), "=r"(r2), "=r"(r3)
                 : "r"(saddr));
}

__device__ __forceinline__ void cp_async16(uint32_t dst, const void* src, int srcsize) {
    asm volatile("cp.async.cg.shared.global [%0], [%1], 16, %2;"
                 :: "r"(dst), "l"(src), "r"(srcsize) : "memory");
}

__device__ __forceinline__ void mma16816(float* d, const uint32_t* a, const uint32_t* b) {
    asm volatile(
        "mma.sync.aligned.m16n8k16.row.col.f32.f16.f16.f32 "
        "{%0,%1,%2,%3}, {%4,%5,%6,%7}, {%8,%9}, {%0,%1,%2,%3};"
        : "+f"(d[0]), "+f"(d[1]), "+f"(d[2]), "+f"(d[3])
        : "r"(a[0]), "r"(a[1]), "r"(a[2]), "r"(a[3]), "r"(b[0]), "r"(b[1]));
}

// ---- packed fp32x2 (FFMA2) helpers ----
__device__ __forceinline__ uint64_t pk2(float x) {
    uint64_t r;
    asm("mov.b64 %0, {%1, %1};" : "=l"(r) : "f"(x));
    return r;
}
__device__ __forceinline__ void fma2(uint64_t &d, uint64_t a, uint64_t b) {
    asm("fma.rn.f32x2 %0, %1, %2, %0;" : "+l"(d) : "l"(a), "l"(b));
}
__device__ __forceinline__ float2 up2(uint64_t v) {
    float2 r;
    asm("mov.b64 {%0, %1}, %2;" : "=f"(r.x), "=f"(r.y) : "l"(v));
    return r;
}

// ---------------- fp16 tensor-core GEMM, BK=64, 3-stage cp.async pipeline (NT) ----------------
// Dynamic smem: 3 buffers x (A,B) x 128 rows x 72-half stride (144B, ldsm conflict-free).
#define HST   72
#define HBUF  (128 * HST * 2)      // 18432 B per matrix buffer
#define HSMEM (6 * HBUF)           // 110592 B

__global__ __launch_bounds__(256, 2) void hgemm_nt_kernel(
    const __half* __restrict__ A, const __half* __restrict__ B, float* __restrict__ C,
    int M, int N, int K)
{
    extern __shared__ __align__(16) __half hsm[];

    const int tid  = threadIdx.x;
    const int warp = tid >> 5;
    const int lane = tid & 31;
    const int g    = lane >> 2;
    const int t4   = lane & 3;
    const int wm   = (warp >> 1) * 32;
    const int wn   = (warp & 1) * 64;
    const int m0   = blockIdx.y * 128;
    const int n0   = blockIdx.x * 128;

    const int lm  = lane >> 3;
    const int lr  = lane & 7;
    const int arow = (lm & 1) * 8 + lr;
    const int acol = (lm >> 1) * 8;
    const int brow = (lm >> 1) * 8 + lr;
    const int bcol = (lm & 1) * 8;

    const uint32_t as_b = smem_u32(hsm);
    const uint32_t bs_b = as_b + 3u * HBUF;

    float d[2][8][4];
#pragma unroll
    for (int i = 0; i < 2; i++)
#pragma unroll
        for (int j = 0; j < 8; j++)
#pragma unroll
            for (int v = 0; v < 4; v++) d[i][j][v] = 0.0f;

    const int nch = K >> 6;        // K/64 chunks

    auto stage = [&](int kc, int buf) {
        const int kb = kc << 6;
#pragma unroll
        for (int i = 0; i < 4; i++) {
            const int f   = tid + (i << 8);      // 0..1023
            const int row = f >> 3;              // 0..127
            const int seg = f & 7;               // 8 x 16B per 128B row
            const uint32_t off = (uint32_t)(row * (HST * 2) + seg * 16);
            cp_async16(as_b + (uint32_t)buf * HBUF + off,
                       &A[(size_t)(m0 + row) * K + kb + seg * 8], 16);
            const int nr = n0 + row;
            const int ok = (nr < N);
            cp_async16(bs_b + (uint32_t)buf * HBUF + off,
                       &B[(size_t)(ok ? nr : 0) * K + kb + seg * 8], ok ? 16 : 0);
        }
        asm volatile("cp.async.commit_group;" ::: "memory");
    };

    stage(0, 0);
    if (nch > 1) stage(1, 1);

    for (int kc = 0; kc < nch; kc++) {
        const int buf = kc % 3;
        if (kc + 1 < nch) {
            asm volatile("cp.async.wait_group 1;" ::: "memory");
        } else {
            asm volatile("cp.async.wait_group 0;" ::: "memory");
        }
        __syncthreads();
        if (kc + 2 < nch) stage(kc + 2, (kc + 2) % 3);

        const uint32_t ab = as_b + (uint32_t)buf * HBUF;
        const uint32_t bb = bs_b + (uint32_t)buf * HBUF;
#pragma unroll
        for (int s = 0; s < 4; s++) {
            const int kk = s * 16;
            uint32_t af[2][4];
#pragma unroll
            for (int mt = 0; mt < 2; mt++) {
                uint32_t addr = ab + (uint32_t)(((wm + mt * 16 + arow) * HST + kk + acol) * 2);
                ldsm4(af[mt][0], af[mt][1], af[mt][2], af[mt][3], addr);
            }
            uint32_t bf[8][2];
#pragma unroll
            for (int ntp = 0; ntp < 4; ntp++) {
                uint32_t q0, q1, q2, q3;
                uint32_t addr = bb + (uint32_t)(((wn + ntp * 16 + brow) * HST + kk + bcol) * 2);
                ldsm4(q0, q1, q2, q3, addr);
                bf[2 * ntp][0]     = q0;  bf[2 * ntp][1]     = q1;
                bf[2 * ntp + 1][0] = q2;  bf[2 * ntp + 1][1] = q3;
            }
#pragma unroll
            for (int mt = 0; mt < 2; mt++) {
#pragma unroll
                for (int nt = 0; nt < 8; nt++) {
                    mma16816(d[mt][nt], af[mt], bf[nt]);
                }
            }
        }
    }

#pragma unroll
    for (int mt = 0; mt < 2; mt++) {
        const int mrow = m0 + wm + mt * 16;
#pragma unroll
        for (int nt = 0; nt < 8; nt++) {
            const int ncol = n0 + wn + nt * 8 + t4 * 2;
            if (ncol < N) {
                *(float2*)&C[(size_t)(mrow + g    ) * N + ncol] =
                    make_float2(d[mt][nt][0], d[mt][nt][1]);
                *(float2*)&C[(size_t)(mrow + g + 8) * N + ncol] =
                    make_float2(d[mt][nt][2], d[mt][nt][3]);
            }
        }
    }
}

// ---------------- fp32 -> fp16 conversion (vectorized) ----------------
__global__ __launch_bounds__(256) void f2h_kernel(const float* __restrict__ src,
                                                  __half* __restrict__ dst, size_t n)
{
    size_t i = ((size_t)blockIdx.x * blockDim.x + threadIdx.x) * 4;
    if (i >= n) return;
    float4 v = *(const float4*)&src[i];
    __half2* d2 = (__half2*)&dst[i];
    d2[0] = __floats2half2_rn(v.x, v.y);
    d2[1] = __floats2half2_rn(v.z, v.w);
}

// ---------------- conv1d (width 4, causal) + bias + SiLU: 4 t's per thread ----------------
__global__ __launch_bounds__(256) void conv_silu_kernel(
    const float* __restrict__ conv_w, const float* __restrict__ conv_b)
{
    const int TB = LL / 4;
    int idx = blockIdx.x * 256 + threadIdx.x;
    if (idx >= BB * TB * CONVDIM) return;
    const int c  = idx % CONVDIM;
    const int tb = idx / CONVDIM;
    const int t0 = (tb % TB) * 4;
    const int b  = tb / TB;

    const float w0 = conv_w[c * DCONV + 0];
    const float w1 = conv_w[c * DCONV + 1];
    const float w2 = conv_w[c * DCONV + 2];
    const float w3 = conv_w[c * DCONV + 3];
    const float bias = conv_b[c];

    const size_t base = (size_t)(b * LL) * DPROJ + DSSM + c;
    float x[7];
#pragma unroll
    for (int j = 0; j < 7; j++) {
        const int ts = t0 - 3 + j;
        x[j] = (ts >= 0) ? g_zxbcdt[base + (size_t)ts * DPROJ] : 0.0f;
    }
#pragma unroll
    for (int k = 0; k < 4; k++) {
        float acc = bias;
        acc = fmaf(x[k + 0], w0, acc);
        acc = fmaf(x[k + 1], w1, acc);
        acc = fmaf(x[k + 2], w2, acc);
        acc = fmaf(x[k + 3], w3, acc);
        g_xbc[(size_t)(b * LL + t0 + k) * CONVDIM + c] = silu_f(acc);
    }
}

// ---------------- dt softplus + log-decay (transposed layouts) ----------------
__global__ __launch_bounds__(256) void dt_kernel(
    const float* __restrict__ dt_bias, const float* __restrict__ A_log)
{
    int idx = blockIdx.x * blockDim.x + threadIdx.x;
    if (idx >= ROWS * NH) return;
    int h = idx % NH;
    int r = idx / NH;
    float raw = g_zxbcdt[(size_t)r * DPROJ + DSSM + CONVDIM + h] + dt_bias[h];
    float dt = (raw > 20.0f) ? raw : log1pf(expf(raw));
    float Aneg = -expf(A_log[h]);
    g_dtT[(size_t)h * ROWS + r] = dt;
    g_ldAT[(size_t)h * ROWS + r] = dt * Aneg;
}

// ================= Chunked SSD scan =================

// ---------------- Phase A: per-chunk state increment (fp32 FFMA2; fp16 dH store) ----------------
__global__ __launch_bounds__(256) void ssd_phaseA_kernel()
{
    extern __shared__ float sm[];
    float* s_B    = sm;                    // [64][132]
    float* s_wdtx = sm + 64 * 132;         // [64][68]
    float* s_w    = s_wdtx + 64 * 68;      // [64]
    float* s_cl   = s_w + 64;              // [64]

    const int tid = threadIdx.x;
    const int bx  = blockIdx.x;
    const int c   = bx & (NCHUNK - 1);
    const int bh  = bx >> 6;
    const int b   = bh >> 5;
    const int h   = bh & 31;
    const int t0row = b * LL + c * CT;

    if (tid == 0) {
        float cl = 0.f;
        const float* ld = g_ldAT + (size_t)h * ROWS + t0row;
#pragma unroll 4
        for (int t = 0; t < CT; t++) { cl += ld[t]; s_cl[t] = cl; }
    }
#pragma unroll
    for (int i = 0; i < 8; i++) {
        const int f = tid + (i << 8);
        const int row = f >> 5;
        const int q = (f & 31) << 2;
        float4 v = *(const float4*)&g_xbc[(size_t)(t0row + row) * CONVDIM + DSSM + q];
        *(float4*)&s_B[row * 132 + q] = v;
    }
    __syncthreads();

    const float cend = s_cl[CT - 1];
    if (tid < CT) {
        s_w[tid] = expf(cend - s_cl[tid]);
        g_cumlog[(size_t)bx * CT + tid] = s_cl[tid];
        if (tid == 0) g_clend[bx] = cend;
    }
    __syncthreads();

    // coalesced staging: p fast across threads, tau broadcast per 64-thread group
#pragma unroll
    for (int i = 0; i < 16; i++) {
        const int f = tid + (i << 8);
        const int p   = f & 63;
        const int tau = f >> 6;
        const float dt = g_dtT[(size_t)h * ROWS + t0row + tau];
        const float xv = g_xbc[(size_t)(t0row + tau) * CONVDIM + h * HD + p];
        s_wdtx[tau * 68 + p] = s_w[tau] * dt * xv;
    }
    __syncthreads();

    const int pp = tid >> 4;
    const int nu = tid & 15;
    const int p0 = pp << 2;
    const int n0 = nu << 3;
    uint64_t accp[4][4];
#pragma unroll
    for (int i = 0; i < 4; i++)
#pragma unroll
        for (int j = 0; j < 4; j++) accp[i][j] = 0ull;

#pragma unroll 4
    for (int t4_ = 0; t4_ < 16; t4_++) {
        const int tau = t4_ << 2;
        float4 wv[4];
        ulonglong2 bq[4][2];
#pragma unroll
        for (int k = 0; k < 4; k++) {
            wv[k] = *(const float4*)&s_wdtx[(tau + k) * 68 + p0];
            bq[k][0] = *(const ulonglong2*)&s_B[(tau + k) * 132 + n0];
            bq[k][1] = *(const ulonglong2*)&s_B[(tau + k) * 132 + n0 + 4];
        }
#pragma unroll
        for (int k = 0; k < 4; k++) {
            const float* wp = (const float*)&wv[k];
#pragma unroll
            for (int i = 0; i < 4; i++) {
                const uint64_t s = pk2(wp[i]);
                fma2(accp[i][0], s, bq[k][0].x);
                fma2(accp[i][1], s, bq[k][0].y);
                fma2(accp[i][2], s, bq[k][1].x);
                fma2(accp[i][3], s, bq[k][1].y);
            }
        }
    }
    __half* dh = g_dHh + (size_t)bx * (HD * DSTATE);
#pragma unroll
    for (int i = 0; i < 4; i++) {
        const float2 v0 = up2(accp[i][0]);
        const float2 v1 = up2(accp[i][1]);
        const float2 v2 = up2(accp[i][2]);
        const float2 v3 = up2(accp[i][3]);
        __half2 hh[4];
        hh[0] = __floats2half2_rn(v0.x, v0.y);
        hh[1] = __floats2half2_rn(v1.x, v1.y);
        hh[2] = __floats2half2_rn(v2.x, v2.y);
        hh[3] = __floats2half2_rn(v3.x, v3.y);
        *(ulonglong2*)&dh[(p0 + i) * DSTATE + n0] = *(ulonglong2*)hh;
    }
}

// ---------------- Phase B: chunk-level recurrence (fp32 carry; fp16 streams) ----------------
__global__ __launch_bounds__(256) void ssd_phaseB_kernel()
{
    const int gid = blockIdx.x * 256 + threadIdx.x;
    const int bh  = gid >> 11;
    const int e   = (gid & 2047) << 2;

    float4 h = make_float4(0.f, 0.f, 0.f, 0.f);
    const size_t sbase = (size_t)bh * NCHUNK;
    for (int c = 0; c < NCHUNK; c++) {
        const size_t slot = sbase + c;
        const __half2* dsrc = (const __half2*)&g_dHh[slot * (HD * DSTATE) + e];
        const __half2 dh0 = dsrc[0], dh1 = dsrc[1];
        __half2* hp = (__half2*)&g_hpreh[slot * (HD * DSTATE) + e];
        hp[0] = __floats2half2_rn(h.x, h.y);
        hp[1] = __floats2half2_rn(h.z, h.w);
        const float2 d01 = __half22float2(dh0);
        const float2 d23 = __half22float2(dh1);
        const float P = expf(g_clend[slot]);
        h.x = fmaf(h.x, P, d01.x);
        h.y = fmaf(h.y, P, d01.y);
        h.z = fmaf(h.z, P, d23.x);
        h.w = fmaf(h.w, P, d23.y);
    }
}

// ---------------- Phase C: per-chunk output (fp32 FFMA2; smem overlay, 2 CTA/SM) ----------------
#define SMC2 ((64*132 + 128*68 + 128*68 + 64) * 4)   // 103,680 B

__global__ __launch_bounds__(256, 2) void ssd_phaseC_kernel(const float* __restrict__ Dp)
{
    extern __shared__ float sm[];
    float* s_C   = sm;                       // [64][132]
    float* s_X   = sm + 64 * 132;            // [128][68]  B^T; later Gm [64][68]
    float* s_H   = s_X + 128 * 68;           // [128][68]  h^T (fp32 in smem)
    float* s_cl  = s_H + 128 * 68;           // [64]
    float* s_Gm  = s_X;                      // alias (pass2)
    float* s_dtx = s_C;                      // alias (pass2), stride 68

    const int tid = threadIdx.x;
    const int bx  = blockIdx.x;
    const int c   = bx & (NCHUNK - 1);
    const int bh  = bx >> 6;
    const int b   = bh >> 5;
    const int h   = bh & 31;
    const int t0row = b * LL + c * CT;
    const float Dh = Dp[h];

#pragma unroll
    for (int i = 0; i < 8; i++) {
        const int f = tid + (i << 8);
        const int row = f >> 5;
        const int q = (f & 31) << 2;
        float4 cv = *(const float4*)&g_xbc[(size_t)(t0row + row) * CONVDIM + DSSM + DSTATE + q];
        *(float4*)&s_C[row * 132 + q] = cv;
        float4 bv = *(const float4*)&g_xbc[(size_t)(t0row + row) * CONVDIM + DSSM + q];
        s_X[(q + 0) * 68 + row] = bv.x;
        s_X[(q + 1) * 68 + row] = bv.y;
        s_X[(q + 2) * 68 + row] = bv.z;
        s_X[(q + 3) * 68 + row] = bv.w;
        const int p = f >> 5;
        const __half2* hsrc = (const __half2*)&g_hpreh[(size_t)bx * (HD * DSTATE) + p * DSTATE + q];
        const float2 h01 = __half22float2(hsrc[0]);
        const float2 h23 = __half22float2(hsrc[1]);
        s_H[(q + 0) * 68 + p] = h01.x;
        s_H[(q + 1) * 68 + p] = h01.y;
        s_H[(q + 2) * 68 + p] = h23.x;
        s_H[(q + 3) * 68 + p] = h23.y;
    }
    if (tid < CT) s_cl[tid] = g_cumlog[(size_t)bx * CT + tid];
    __syncthreads();

    const int tt = tid >> 4;
    const int tu = tid & 15;
    const int t0 = tt << 2;
    const int u0 = tu << 2;

    uint64_t y2[4][2];
    uint64_t gp[4][2];
#pragma unroll
    for (int i = 0; i < 4; i++) {
        y2[i][0] = 0ull; y2[i][1] = 0ull;
        gp[i][0] = 0ull; gp[i][1] = 0ull;
    }

    // ---- fused pass1: G = C @ B^T  AND  Y2 = C @ h^T (shared cv loads) ----
#pragma unroll 2
    for (int n4 = 0; n4 < 32; n4++) {
        const int n = n4 << 2;
        float4 cv[4];
        ulonglong2 bq[4], hq[4];
#pragma unroll
        for (int i = 0; i < 4; i++) cv[i] = *(const float4*)&s_C[(t0 + i) * 132 + n];
#pragma unroll
        for (int k = 0; k < 4; k++) {
            bq[k] = *(const ulonglong2*)&s_X[(n + k) * 68 + u0];
            hq[k] = *(const ulonglong2*)&s_H[(n + k) * 68 + u0];
        }
#pragma unroll
        for (int k = 0; k < 4; k++) {
#pragma unroll
            for (int i = 0; i < 4; i++) {
                const uint64_t s = pk2(((const float*)&cv[i])[k]);
                fma2(gp[i][0], s, bq[k].x);
                fma2(gp[i][1], s, bq[k].y);
                fma2(y2[i][0], s, hq[k].x);
                fma2(y2[i][1], s, hq[k].y);
            }
        }
    }
    __syncthreads();   // everyone done READING s_C / s_X before overwrite

    // mask + decay -> Gm (overwrites s_X region)
#pragma unroll
    for (int i = 0; i < 4; i++) {
        const int t = t0 + i;
        const float clt = s_cl[t];
        const float2 a01 = up2(gp[i][0]);
        const float2 a23 = up2(gp[i][1]);
        const float av[4] = {a01.x, a01.y, a23.x, a23.y};
#pragma unroll
        for (int j = 0; j < 4; j++) {
            const int u = u0 + j;
            s_Gm[t * 68 + u] = (u <= t) ? expf(clt - s_cl[u]) * av[j] : 0.f;
        }
    }
    // stage dtx (overwrites s_C region, stride 68) — coalesced: p fast, tau broadcast
#pragma unroll
    for (int i = 0; i < 16; i++) {
        const int f = tid + (i << 8);
        const int p   = f & 63;
        const int tau = f >> 6;
        const float dt = g_dtT[(size_t)h * ROWS + t0row + tau];
        const float xv = g_xbc[(size_t)(t0row + tau) * CONVDIM + h * HD + p];
        s_dtx[tau * 68 + p] = dt * xv;
    }
    __syncthreads();

    // ---- pass2: Y1 = Gm @ dtx; combine with Y2, D*x epilogue ----
    {
        const int p0 = tu << 2;
        uint64_t y1[4][2];
#pragma unroll
        for (int i = 0; i < 4; i++) { y1[i][0] = 0ull; y1[i][1] = 0ull; }

#pragma unroll 4
        for (int u4 = 0; u4 < 16; u4++) {
            const int u = u4 << 2;
            float4 gv[4];
            ulonglong2 dq[4];
#pragma unroll
            for (int i = 0; i < 4; i++) gv[i] = *(const float4*)&s_Gm[(t0 + i) * 68 + u];
#pragma unroll
            for (int k = 0; k < 4; k++) dq[k] = *(const ulonglong2*)&s_dtx[(u + k) * 68 + p0];
#pragma unroll
            for (int k = 0; k < 4; k++) {
#pragma unroll
                for (int i = 0; i < 4; i++) {
                    const uint64_t s = pk2(((const float*)&gv[i])[k]);
                    fma2(y1[i][0], s, dq[k].x);
                    fma2(y1[i][1], s, dq[k].y);
                }
            }
        }
#pragma unroll
        for (int i = 0; i < 4; i++) {
            const int t = t0 + i;
            const int row = t0row + t;
            const float et = expf(s_cl[t]);
            const float2 a01 = up2(y1[i][0]);
            const float2 a23 = up2(y1[i][1]);
            const float2 b01 = up2(y2[i][0]);
            const float2 b23 = up2(y2[i][1]);
            float4 xv = *(const float4*)&g_xbc[(size_t)row * CONVDIM + h * HD + p0];
            float4 y4;
            y4.x = fmaf(et, b01.x, a01.x) + Dh * xv.x;
            y4.y = fmaf(et, b01.y, a01.y) + Dh * xv.y;
            y4.z = fmaf(et, b23.x, a23.x) + Dh * xv.z;
            y4.w = fmaf(et, b23.y, a23.y) + Dh * xv.w;
            *(float4*)&g_y[(size_t)row * DSSM + h * HD + p0] = y4;
        }
    }
}

// ---------------- gate (silu(z)) + RMSNorm -> fp16 output for GEMM2 ----------------
__global__ __launch_bounds__(256) void gate_rmsnorm_kernel(const float* __restrict__ norm_w)
{
    const int row = blockIdx.x;
    const int tid = threadIdx.x;
    const int w = tid >> 5, lane = tid & 31;

    float vals[8];
    float ss = 0.f;
#pragma unroll
    for (int i = 0; i < 8; i++) {
        int e = i * 256 + tid;
        float z = g_zxbcdt[(size_t)row * DPROJ + e];
        float yv = g_y[(size_t)row * DSSM + e];
        float g = yv * silu_f(z);
        vals[i] = g;
        ss = fmaf(g, g, ss);
    }
    ss += __shfl_xor_sync(0xffffffffu, ss, 16);
    ss += __shfl_xor_sync(0xffffffffu, ss, 8);
    ss += __shfl_xor_sync(0xffffffffu, ss, 4);
    ss += __shfl_xor_sync(0xffffffffu, ss, 2);
    ss += __shfl_xor_sync(0xffffffffu, ss, 1);

    __shared__ float red[8];
    __shared__ float sscale;
    if (lane == 0) red[w] = ss;
    __syncthreads();
    if (tid == 0) {
        float s = 0.f;
#pragma unroll
        for (int k = 0; k < 8; k++) s += red[k];
        sscale = rsqrtf(s / (float)DSSM + EPSV);
    }
    __syncthreads();
    const float scale = sscale;
#pragma unroll
    for (int i = 0; i < 8; i++) {
        int e = i * 256 + tid;
        g_gh[(size_t)row * DSSM + e] = __float2half(vals[i] * scale * norm_w[e]);
    }
}

// ---------------- entry ----------------
extern "C" void kernel_launch(void* const* d_in, const int* in_sizes, int n_in,
                              void* d_out, int out_size)
{
    const float* u       = (const float*)d_in[0];
    const float* W_in    = (const float*)d_in[1];
    const float* conv_w  = (const float*)d_in[2];
    const float* conv_b  = (const float*)d_in[3];
    const float* dt_bias = (const float*)d_in[4];
    const float* A_log   = (const float*)d_in[5];
    const float* Dp      = (const float*)d_in[6];
    const float* norm_w  = (const float*)d_in[7];
    const float* W_out   = (const float*)d_in[8];
    float* out = (float*)d_out;

    float*  zx;  cudaGetSymbolAddress((void**)&zx,  g_zxbcdt);
    __half* uh;  cudaGetSymbolAddress((void**)&uh,  g_uh);
    __half* wih; cudaGetSymbolAddress((void**)&wih, g_Winh);
    __half* gh;  cudaGetSymbolAddress((void**)&gh,  g_gh);
    __half* woh; cudaGetSymbolAddress((void**)&woh, g_Wouth);

    const int smA = (64 * 132 + 64 * 68 + 64 + 64) * 4;
    cudaFuncSetAttribute(hgemm_nt_kernel, cudaFuncAttributeMaxDynamicSharedMemorySize, HSMEM);
    cudaFuncSetAttribute(ssd_phaseA_kernel, cudaFuncAttributeMaxDynamicSharedMemorySize, smA);
    cudaFuncSetAttribute(ssd_phaseC_kernel, cudaFuncAttributeMaxDynamicSharedMemorySize, SMC2);

    // 0) fp16 conversions
    {
        size_t nu = (size_t)ROWS * DMODEL;
        f2h_kernel<<<(unsigned)((nu / 4 + 255) / 256), 256>>>(u, uh, nu);
        size_t nw = (size_t)DPROJ * DMODEL;
        f2h_kernel<<<(unsigned)((nw / 4 + 255) / 256), 256>>>(W_in, wih, nw);
        size_t no = (size_t)DMODEL * DSSM;
        f2h_kernel<<<(unsigned)((no / 4 + 255) / 256), 256>>>(W_out, woh, no);
    }
    // 1) in-projection
    {
        dim3 grid((DPROJ + 127) / 128, ROWS / 128);
        hgemm_nt_kernel<<<grid, 256, HSMEM>>>(uh, wih, zx, ROWS, DPROJ, DMODEL);
    }
    // 2) conv + silu (4 t's per thread)
    {
        int total = BB * (LL / 4) * CONVDIM;
        conv_silu_kernel<<<(total + 255) / 256, 256>>>(conv_w, conv_b);
    }
    // 3) dt softplus + log decay
    dt_kernel<<<(ROWS * NH + 255) / 256, 256>>>(dt_bias, A_log);
    // 4) chunked SSD scan
    ssd_phaseA_kernel<<<NSLOT, 256, smA>>>();
    ssd_phaseB_kernel<<<512, 256>>>();
    ssd_phaseC_kernel<<<NSLOT, 256, SMC2>>>(Dp);
    // 5) gate + rmsnorm
    gate_rmsnorm_kernel<<<ROWS, 256>>>(norm_w);
    // 6) out-projection
    {
        dim3 grid(DMODEL / 128, ROWS / 128);
        hgemm_nt_kernel<<<grid, 256, HSMEM>>>(gh, woh, out, ROWS, DMODEL, DSSM);
    }
}